// round 1
// baseline (speedup 1.0000x reference)
#include <cuda_runtime.h>
#include <math.h>

// Problem constants
#define CB 4
#define CS 2048
#define CE 1024
#define CH 4
#define CD 256
#define CBH 16      // B*H
#define CM 8192     // B*S tokens

// ---------------- scratch (static device memory; no allocs) ----------------
__device__ float g_q   [(size_t)CM * CE];
__device__ float g_k   [(size_t)CM * CE];
__device__ float g_v   [(size_t)CM * CE];
__device__ float g_sq  [(size_t)CM * CE];
__device__ float g_sk  [(size_t)CM * CE];
__device__ float g_amem[(size_t)CM * CE];
__device__ float g_U   [(size_t)CM * CE];
__device__ float g_mix [(size_t)CM * CE];
__device__ float g_P   [(size_t)CBH * CS * CS];   // 256 MB attention scores
__device__ float g_denq[CBH * CS];
__device__ float g_denk[CBH * CS];

// ---------------------------------------------------------------------------
// Generic 128x128x8 SGEMM (NN), 256 threads, 8x8 per thread.
// EPI: 0 plain store | 2 A_mem (acc/(den+1e-6)) | 3 U = v - acc/(den+1e-6)
//      4 PV + gate-mix with A_mem | 5 +bias
// grid.z = bh pair for EPI 2/3/4 (head-view offsets computed inside).
// All dims are multiples of the tile sizes for this problem; no bounds checks.
// ---------------------------------------------------------------------------
template <int EPI>
__global__ void __launch_bounds__(256, 2)
sgemm_nn(const float* __restrict__ Ag, const float* __restrict__ Bg,
         float* __restrict__ Cg, int M, int N, int K,
         int lda, int ldb, int ldc,
         const float* __restrict__ aux0, const float* __restrict__ aux1)
{
    const int z = blockIdx.z;
    size_t offA = 0, offB = 0, offC = 0;
    const float* den  = nullptr;
    const float* vsrc = nullptr;
    const float* amem = nullptr;
    float gate = 0.f, omg = 0.f;
    if (EPI == 2 || EPI == 3) {
        const int b = z / CH, h = z % CH;
        offA = (size_t)b * CS * CE + (size_t)h * CD;
        offB = (size_t)h * CD * CD;
        offC = offA;
        den  = aux0 + (size_t)z * CS;
        if (EPI == 3) vsrc = aux1 + offA;
    } else if (EPI == 4) {
        const int b = z / CH, h = z % CH;
        offA = (size_t)z * CS * CS;
        offB = (size_t)b * CS * CE + (size_t)h * CD;
        offC = offB;
        amem = aux0 + offB;
        gate = 1.f / (1.f + __expf(-aux1[h]));
        omg  = 1.f - gate;
    }
    const float* A  = Ag + offA;
    const float* Bm = Bg + offB;
    float*       C  = Cg + offC;

    const int m0 = blockIdx.y * 128;
    const int n0 = blockIdx.x * 128;
    int Keff = K;
    if (EPI == 4) Keff = min(K, m0 + 128);   // causal: P[m][k]==0 for k>m

    __shared__ __align__(16) float As[8][128];
    __shared__ __align__(16) float Bs[8][128];

    float acc[8][8];
#pragma unroll
    for (int i = 0; i < 8; i++)
#pragma unroll
        for (int j = 0; j < 8; j++) acc[i][j] = 0.f;

    const int tid = threadIdx.x;
    const int a_m = tid >> 1;
    const int a_k = (tid & 1) * 4;
    const int b_k = tid >> 5;
    const int b_n = (tid & 31) * 4;
    const int tx = tid & 15, ty = tid >> 4;

    for (int k0 = 0; k0 < Keff; k0 += 8) {
        float4 av = *(const float4*)(A + (size_t)(m0 + a_m) * lda + k0 + a_k);
        As[a_k + 0][a_m] = av.x; As[a_k + 1][a_m] = av.y;
        As[a_k + 2][a_m] = av.z; As[a_k + 3][a_m] = av.w;
        *(float4*)(&Bs[b_k][b_n]) =
            *(const float4*)(Bm + (size_t)(k0 + b_k) * ldb + n0 + b_n);
        __syncthreads();
#pragma unroll
        for (int kk = 0; kk < 8; kk++) {
            float a[8], b[8];
            *(float4*)(a)     = *(const float4*)(&As[kk][ty * 4]);
            *(float4*)(a + 4) = *(const float4*)(&As[kk][ty * 4 + 64]);
            *(float4*)(b)     = *(const float4*)(&Bs[kk][tx * 4]);
            *(float4*)(b + 4) = *(const float4*)(&Bs[kk][tx * 4 + 64]);
#pragma unroll
            for (int i = 0; i < 8; i++)
#pragma unroll
                for (int j = 0; j < 8; j++)
                    acc[i][j] = fmaf(a[i], b[j], acc[i][j]);
        }
        __syncthreads();
    }

#pragma unroll
    for (int i = 0; i < 8; i++) {
        const int m = m0 + ty * 4 + (i < 4 ? i : 60 + i);
#pragma unroll
        for (int j = 0; j < 8; j++) {
            const int n = n0 + tx * 4 + (j < 4 ? j : 60 + j);
            const size_t idx = (size_t)m * ldc + n;
            float v = acc[i][j];
            if (EPI == 2)      v = v / (den[m] + 1e-6f);
            else if (EPI == 3) v = vsrc[idx] - v / (den[m] + 1e-6f);
            else if (EPI == 4) v = gate * amem[idx] + omg * v;
            else if (EPI == 5) v = v + aux0[n];
            C[idx] = v;
        }
    }
}

// ---------------------------------------------------------------------------
// QK^T (NT): P[m][n] = sum_d q[m,d]*k[n,d], causal mask in epilogue,
// fully-masked tiles early-out with -1e30 fill.
// ---------------------------------------------------------------------------
__global__ void __launch_bounds__(256, 2)
sgemm_nt_qk(const float* __restrict__ qg, const float* __restrict__ kg,
            float* __restrict__ Pg)
{
    const int z = blockIdx.z;
    const int b = z / CH, h = z % CH;
    const size_t off = (size_t)b * CS * CE + (size_t)h * CD;
    const float* A  = qg + off;
    const float* Bm = kg + off;
    float*       C  = Pg + (size_t)z * CS * CS;

    const int m0 = blockIdx.y * 128;
    const int n0 = blockIdx.x * 128;
    const int tid = threadIdx.x;
    const int tx = tid & 15, ty = tid >> 4;

    if (n0 > m0 + 127) {  // entirely above diagonal: masked
#pragma unroll
        for (int i = 0; i < 8; i++) {
            const int m = m0 + ty * 4 + (i < 4 ? i : 60 + i);
#pragma unroll
            for (int j = 0; j < 8; j++) {
                const int n = n0 + tx * 4 + (j < 4 ? j : 60 + j);
                C[(size_t)m * CS + n] = -1e30f;
            }
        }
        return;
    }

    __shared__ __align__(16) float As[8][128];
    __shared__ __align__(16) float Bs[8][128];

    float acc[8][8];
#pragma unroll
    for (int i = 0; i < 8; i++)
#pragma unroll
        for (int j = 0; j < 8; j++) acc[i][j] = 0.f;

    const int a_m = tid >> 1;
    const int a_k = (tid & 1) * 4;

    for (int k0 = 0; k0 < CD; k0 += 8) {
        float4 av = *(const float4*)(A + (size_t)(m0 + a_m) * CE + k0 + a_k);
        As[a_k + 0][a_m] = av.x; As[a_k + 1][a_m] = av.y;
        As[a_k + 2][a_m] = av.z; As[a_k + 3][a_m] = av.w;
        float4 bv = *(const float4*)(Bm + (size_t)(n0 + a_m) * CE + k0 + a_k);
        Bs[a_k + 0][a_m] = bv.x; Bs[a_k + 1][a_m] = bv.y;
        Bs[a_k + 2][a_m] = bv.z; Bs[a_k + 3][a_m] = bv.w;
        __syncthreads();
#pragma unroll
        for (int kk = 0; kk < 8; kk++) {
            float a[8], b[8];
            *(float4*)(a)     = *(const float4*)(&As[kk][ty * 4]);
            *(float4*)(a + 4) = *(const float4*)(&As[kk][ty * 4 + 64]);
            *(float4*)(b)     = *(const float4*)(&Bs[kk][tx * 4]);
            *(float4*)(b + 4) = *(const float4*)(&Bs[kk][tx * 4 + 64]);
#pragma unroll
            for (int i = 0; i < 8; i++)
#pragma unroll
                for (int j = 0; j < 8; j++)
                    acc[i][j] = fmaf(a[i], b[j], acc[i][j]);
        }
        __syncthreads();
    }

#pragma unroll
    for (int i = 0; i < 8; i++) {
        const int m = m0 + ty * 4 + (i < 4 ? i : 60 + i);
#pragma unroll
        for (int j = 0; j < 8; j++) {
            const int n = n0 + tx * 4 + (j < 4 ? j : 60 + j);
            C[(size_t)m * CS + n] = (n <= m) ? acc[i][j] : -1e30f;
        }
    }
}

// ---------------------------------------------------------------------------
// mem_new (TN, 64x64 tiles): C[d][e] = mem[h][d][e] + sum_s sk[s,d]*U[s,e]
// ---------------------------------------------------------------------------
__global__ void __launch_bounds__(256)
sgemm_tn_mem(const float* __restrict__ skg, const float* __restrict__ Ug,
             const float* __restrict__ memg, float* __restrict__ outp)
{
    const int z = blockIdx.z;
    const int b = z / CH, h = z % CH;
    const size_t off = (size_t)b * CS * CE + (size_t)h * CD;
    const float* A  = skg + off;
    const float* Bm = Ug + off;
    const int m0 = blockIdx.y * 64, n0 = blockIdx.x * 64;

    __shared__ __align__(16) float As[16][64];
    __shared__ __align__(16) float Bs[16][64];
    float acc[4][4];
#pragma unroll
    for (int i = 0; i < 4; i++)
#pragma unroll
        for (int j = 0; j < 4; j++) acc[i][j] = 0.f;

    const int tid = threadIdx.x;
    const int lk = tid >> 4;
    const int lm = (tid & 15) * 4;
    const int tx = tid & 15, ty = tid >> 4;

    for (int k0 = 0; k0 < CS; k0 += 16) {
        *(float4*)(&As[lk][lm]) = *(const float4*)(A + (size_t)(k0 + lk) * CE + m0 + lm);
        *(float4*)(&Bs[lk][lm]) = *(const float4*)(Bm + (size_t)(k0 + lk) * CE + n0 + lm);
        __syncthreads();
#pragma unroll
        for (int kk = 0; kk < 16; kk++) {
            float a[4], b[4];
            *(float4*)a = *(const float4*)(&As[kk][ty * 4]);
            *(float4*)b = *(const float4*)(&Bs[kk][tx * 4]);
#pragma unroll
            for (int i = 0; i < 4; i++)
#pragma unroll
                for (int j = 0; j < 4; j++)
                    acc[i][j] = fmaf(a[i], b[j], acc[i][j]);
        }
        __syncthreads();
    }

    const size_t memoff = (size_t)CM * CE;
#pragma unroll
    for (int i = 0; i < 4; i++) {
        const int d = m0 + ty * 4 + i;
#pragma unroll
        for (int j = 0; j < 4; j++) {
            const int e = n0 + tx * 4 + j;
            outp[memoff + ((size_t)z * CD + d) * CD + e] =
                memg[(size_t)h * CD * CD + (size_t)d * CD + e] + acc[i][j];
        }
    }
}

// ---------------------------------------------------------------------------
// elementwise sigma = elu(x)+1  (x>0 ? x+1 : exp(x))
// ---------------------------------------------------------------------------
__global__ void sigma_kernel(const float* __restrict__ q, const float* __restrict__ k,
                             float* __restrict__ sq, float* __restrict__ sk)
{
    const size_t i = (size_t)blockIdx.x * blockDim.x + threadIdx.x;
    const float x = q[i];
    sq[i] = (x > 0.f) ? x + 1.f : __expf(x);
    const float y = k[i];
    sk[i] = (y > 0.f) ? y + 1.f : __expf(y);
}

// denq[bh][s] = sigma_q[row] . z_h ; denk likewise. One warp per row.
__global__ void denom_kernel(const float* __restrict__ sq, const float* __restrict__ sk,
                             const float* __restrict__ zv,
                             float* __restrict__ denq, float* __restrict__ denk)
{
    const int z = blockIdx.y;
    const int b = z / CH, h = z % CH;
    const int warp = threadIdx.x >> 5, lane = threadIdx.x & 31;
    const int s = blockIdx.x * 8 + warp;
    const size_t base = (size_t)(b * CS + s) * CE + (size_t)h * CD;
    const float* zp = zv + h * CD;
    float aq = 0.f, ak = 0.f;
#pragma unroll
    for (int d = lane; d < CD; d += 32) {
        const float zz = zp[d];
        aq = fmaf(sq[base + d], zz, aq);
        ak = fmaf(sk[base + d], zz, ak);
    }
#pragma unroll
    for (int o = 16; o > 0; o >>= 1) {
        aq += __shfl_xor_sync(0xffffffffu, aq, o);
        ak += __shfl_xor_sync(0xffffffffu, ak, o);
    }
    if (lane == 0) {
        denq[z * CS + s] = aq;
        denk[z * CS + s] = ak;
    }
}

// z_new[b,h,d] = z[h,d] + sum_s sigma_k[b,h,s,d]
__global__ void znew_kernel(const float* __restrict__ sk, const float* __restrict__ zv,
                            float* __restrict__ outz)
{
    const int z = blockIdx.x;
    const int b = z / CH, h = z % CH;
    const int d = threadIdx.x;
    float sum = zv[h * CD + d];
    const float* p = sk + (size_t)b * CS * CE + (size_t)h * CD + d;
    for (int s = 0; s < CS; s += 8) {
        float t = 0.f;
#pragma unroll
        for (int u = 0; u < 8; u++) t += p[(size_t)(s + u) * CE];
        sum += t;
    }
    outz[(size_t)z * CD + d] = sum;
}

// row softmax, one warp per row (length CS)
__global__ void softmax_kernel(float* __restrict__ P)
{
    const int z = blockIdx.y;
    const int warp = threadIdx.x >> 5, lane = threadIdx.x & 31;
    const int row = blockIdx.x * 8 + warp;
    float* p = P + (size_t)z * CS * CS + (size_t)row * CS;
    float m = -3.0e38f;
    for (int j = lane; j < CS; j += 32) m = fmaxf(m, p[j]);
#pragma unroll
    for (int o = 16; o > 0; o >>= 1) m = fmaxf(m, __shfl_xor_sync(0xffffffffu, m, o));
    float sum = 0.f;
    for (int j = lane; j < CS; j += 32) sum += __expf(p[j] - m);
#pragma unroll
    for (int o = 16; o > 0; o >>= 1) sum += __shfl_xor_sync(0xffffffffu, sum, o);
    const float inv = 1.f / sum;
    for (int j = lane; j < CS; j += 32) p[j] = __expf(p[j] - m) * inv;
}

// ---------------------------------------------------------------------------
extern "C" void kernel_launch(void* const* d_in, const int* in_sizes, int n_in,
                              void* d_out, int out_size)
{
    (void)in_sizes; (void)n_in; (void)out_size;
    const float* X     = (const float*)d_in[0];
    const float* Wq    = (const float*)d_in[1];
    const float* Wk    = (const float*)d_in[2];
    const float* Wv    = (const float*)d_in[3];
    const float* Wo    = (const float*)d_in[4];
    const float* bo    = (const float*)d_in[5];
    const float* betas = (const float*)d_in[6];
    const float* memp  = (const float*)d_in[7];
    const float* zp    = (const float*)d_in[8];
    float* out = (float*)d_out;

    float *pq, *pk, *pv, *psq, *psk, *pamem, *pU, *pmix, *pP, *pdq, *pdk;
    cudaGetSymbolAddress((void**)&pq,    g_q);
    cudaGetSymbolAddress((void**)&pk,    g_k);
    cudaGetSymbolAddress((void**)&pv,    g_v);
    cudaGetSymbolAddress((void**)&psq,   g_sq);
    cudaGetSymbolAddress((void**)&psk,   g_sk);
    cudaGetSymbolAddress((void**)&pamem, g_amem);
    cudaGetSymbolAddress((void**)&pU,    g_U);
    cudaGetSymbolAddress((void**)&pmix,  g_mix);
    cudaGetSymbolAddress((void**)&pP,    g_P);
    cudaGetSymbolAddress((void**)&pdq,   g_denq);
    cudaGetSymbolAddress((void**)&pdk,   g_denk);

    const dim3 blk(256);
    const dim3 gBig(CE / 128, CM / 128, 1);        // 8 x 64
    const dim3 gHead(CD / 128, CS / 128, CBH);     // 2 x 16 x 16
    const dim3 gQK(CS / 128, CS / 128, CBH);       // 16 x 16 x 16
    const dim3 gMem(CD / 64, CD / 64, CBH);        // 4 x 4 x 16

    // 1) projections
    sgemm_nn<0><<<gBig, blk>>>(X, Wq, pq, CM, CE, CE, CE, CE, CE, nullptr, nullptr);
    sgemm_nn<0><<<gBig, blk>>>(X, Wk, pk, CM, CE, CE, CE, CE, CE, nullptr, nullptr);
    sgemm_nn<0><<<gBig, blk>>>(X, Wv, pv, CM, CE, CE, CE, CE, CE, nullptr, nullptr);

    // 2) feature maps + denominators + z_new
    sigma_kernel<<<(unsigned)((size_t)CM * CE / 256), 256>>>(pq, pk, psq, psk);
    denom_kernel<<<dim3(CS / 8, CBH), 256>>>(psq, psk, zp, pdq, pdk);
    znew_kernel<<<CBH, CD>>>(psk, zp, out + (size_t)CM * CE + (size_t)CBH * CD * CD);

    // 3) compressive-memory read:  A_mem = (sq @ mem) / (sq.z + 1e-6)
    sgemm_nn<2><<<gHead, blk>>>(psq, memp, pamem, CS, CD, CD, CE, CD, CE, pdq, nullptr);

    // 4) causal softmax attention (materialized scores)
    sgemm_nt_qk<<<gQK, blk>>>(pq, pk, pP);
    softmax_kernel<<<dim3(CS / 8, CBH), 256>>>(pP);
    // PV with gate-mix epilogue -> g_mix (token-major [M,E])
    sgemm_nn<4><<<gHead, blk>>>(pP, pv, pmix, CS, CD, CS, CS, CE, CE, pamem, betas);

    // 5) memory update:  U = v - (sk @ mem)/(sk.z+1e-6);  mem_new = mem + sk^T U
    sgemm_nn<3><<<gHead, blk>>>(psk, memp, pU, CS, CD, CD, CE, CD, CE, pdk, pv);
    sgemm_tn_mem<<<gMem, blk>>>(psk, pU, memp, out);

    // 6) output projection + bias
    sgemm_nn<5><<<gBig, blk>>>(pmix, Wo, out, CM, CE, CE, CE, CE, CE, bo, nullptr);
}

// round 3
// speedup vs baseline: 2.0993x; 2.0993x over previous
#include <cuda_runtime.h>
#include <cuda_bf16.h>
#include <cstdint>
#include <math.h>

// Problem constants
#define CB 4
#define CS 2048
#define CE 1024
#define CH 4
#define CD 256
#define CBH 16      // B*H
#define CM 8192     // B*S tokens

// ---------------- f32 scratch ----------------
__device__ float g_q   [(size_t)CM * CE];
__device__ float g_k   [(size_t)CM * CE];
__device__ float g_v   [(size_t)CM * CE];
__device__ float g_sq  [(size_t)CM * CE];
__device__ float g_sk  [(size_t)CM * CE];
__device__ float g_amem[(size_t)CM * CE];
__device__ float g_U   [(size_t)CM * CE];
__device__ float g_mix [(size_t)CM * CE];
__device__ float g_P   [(size_t)CBH * CS * CS];   // f32 logits
__device__ float g_denq[CBH * CS];
__device__ float g_denk[CBH * CS];

// ---------------- bf16 scratch (uint4-typed for 16B alignment) ----------------
__device__ uint4 g_xh [(size_t)CM * CE / 8];
__device__ uint4 g_xl [(size_t)CM * CE / 8];
__device__ uint4 g_qh [(size_t)CM * CE / 8];
__device__ uint4 g_ql [(size_t)CM * CE / 8];
__device__ uint4 g_kh [(size_t)CM * CE / 8];
__device__ uint4 g_kl [(size_t)CM * CE / 8];
__device__ uint4 g_mh [(size_t)CM * CE / 8];
__device__ uint4 g_ml [(size_t)CM * CE / 8];
__device__ uint4 g_wqh[(size_t)CE * CE / 8];
__device__ uint4 g_wql[(size_t)CE * CE / 8];
__device__ uint4 g_wkh[(size_t)CE * CE / 8];
__device__ uint4 g_wkl[(size_t)CE * CE / 8];
__device__ uint4 g_wvh[(size_t)CE * CE / 8];
__device__ uint4 g_wvl[(size_t)CE * CE / 8];
__device__ uint4 g_woh[(size_t)CE * CE / 8];
__device__ uint4 g_wol[(size_t)CE * CE / 8];
__device__ uint4 g_ph [(size_t)CBH * CS * CS / 8];  // softmax probs hi
__device__ uint4 g_pl [(size_t)CBH * CS * CS / 8];  // softmax probs lo
__device__ uint4 g_vth[(size_t)CBH * CD * CS / 8];  // v^T per head hi
__device__ uint4 g_vtl[(size_t)CBH * CD * CS / 8];

// ======================= helpers =======================
__device__ __forceinline__ uint32_t smem_u32(const void* p) {
    uint32_t a;
    asm("{ .reg .u64 t; cvta.to.shared.u64 t, %1; cvt.u32.u64 %0, t; }" : "=r"(a) : "l"(p));
    return a;
}
#define CPA16(dst, src) \
    asm volatile("cp.async.cg.shared.global [%0], [%1], 16;" :: "r"(dst), "l"(src))
#define CP_COMMIT() asm volatile("cp.async.commit_group;")
#define CP_WAIT1()  asm volatile("cp.async.wait_group 1;")

#define LDSM4(r, addr) \
    asm volatile("ldmatrix.sync.aligned.m8n8.x4.shared.b16 {%0,%1,%2,%3}, [%4];" \
        : "=r"((r)[0]), "=r"((r)[1]), "=r"((r)[2]), "=r"((r)[3]) : "r"(addr))

#define MMA16816(d, a, b0, b1) \
    asm volatile("mma.sync.aligned.m16n8k16.row.col.f32.bf16.bf16.f32 " \
        "{%0,%1,%2,%3}, {%4,%5,%6,%7}, {%8,%9}, {%0,%1,%2,%3};" \
        : "+f"((d)[0]), "+f"((d)[1]), "+f"((d)[2]), "+f"((d)[3]) \
        : "r"((a)[0]), "r"((a)[1]), "r"((a)[2]), "r"((a)[3]), "r"(b0), "r"(b1))

// ===========================================================================
// HMMA split-bf16 GEMM: C[M,N] = A·B^T.
// A: [rows, K] K-major (lda). B: [cols, K] K-major (ldb). C f32 (ldc).
// 3 mma per tile pair: Ah·Bh + Ah·Bl + Al·Bh.
// Tile 128x128, KT=64, 2-stage cp.async pipeline, 8 warps (4M x 2N).
// EPI: 0 plain | 1 +bias(aux0) | 2 QK (z=bh offsets, skip masked tiles)
//      3 PV gate-mix (z=bh, causal K clamp, aux0=amem, aux1=betas)
// ===========================================================================
#define HM_SMEM (2 * 65536 + 1024)

template <int EPI>
__global__ void __launch_bounds__(256, 1)
hmma_gemm(const __nv_bfloat16* __restrict__ Ah, const __nv_bfloat16* __restrict__ Al,
          const __nv_bfloat16* __restrict__ Bh, const __nv_bfloat16* __restrict__ Bl,
          float* __restrict__ Cg, int K, int lda, int ldb, int ldc,
          const float* __restrict__ aux0, const float* __restrict__ aux1)
{
    const int m0 = blockIdx.y * 128, n0 = blockIdx.x * 128;
    size_t offA = 0, offB = 0, offC = 0;
    const float* amem = nullptr;
    float gate = 0.f, omg = 0.f;
    int Keff = K;
    if (EPI == 2) {
        if (n0 >= m0 + 128) return;   // fully masked tile: softmax never reads it
        const int z = blockIdx.z, b = z / CH, h = z % CH;
        offA = offB = (size_t)b * CS * CE + (size_t)h * CD;
        offC = (size_t)z * CS * CS;
    } else if (EPI == 3) {
        const int z = blockIdx.z, b = z / CH, h = z % CH;
        offA = (size_t)z * CS * CS;
        offB = (size_t)z * CD * CS;
        offC = (size_t)b * CS * CE + (size_t)h * CD;
        amem = aux0 + offC;
        gate = 1.f / (1.f + __expf(-aux1[z % CH]));
        omg  = 1.f - gate;
        Keff = min(K, m0 + 128);      // probs zero-filled beyond row, clamp K work
    }

    extern __shared__ char dsm_raw[];
    char* base = dsm_raw + ((1024 - (smem_u32(dsm_raw) & 1023)) & 1023);
    const uint32_t sb = smem_u32(base);

    const int tid = threadIdx.x;
    const int wid = tid >> 5, lane = tid & 31;
    const int wm = wid & 3, wn = wid >> 2;

    const __nv_bfloat16* pAh = Ah + offA;
    const __nv_bfloat16* pAl = Al + offA;
    const __nv_bfloat16* pBh = Bh + offB;
    const __nv_bfloat16* pBl = Bl + offB;

    auto load_stage = [&](int kt, int stage) {
        const int k0 = kt * 64;
        const uint32_t sbase = sb + stage * 65536;
#pragma unroll
        for (int it = 0; it < 16; it++) {
            const int mat = it >> 2;                 // compile-time per unrolled it
            const int rem = tid + (it & 3) * 256;    // 0..1023
            const int row = rem >> 3, k8 = rem & 7;
            const uint32_t dst = sbase + mat * 16384 + row * 128 + ((k8 ^ (row & 7)) << 4);
            const __nv_bfloat16* src;
            if (mat == 0)      src = pAh + (size_t)(m0 + row) * lda + k0 + k8 * 8;
            else if (mat == 1) src = pAl + (size_t)(m0 + row) * lda + k0 + k8 * 8;
            else if (mat == 2) src = pBh + (size_t)(n0 + row) * ldb + k0 + k8 * 8;
            else               src = pBl + (size_t)(n0 + row) * ldb + k0 + k8 * 8;
            CPA16(dst, src);
        }
    };

    float acc[2][8][4];
#pragma unroll
    for (int mi = 0; mi < 2; mi++)
#pragma unroll
        for (int nj = 0; nj < 8; nj++)
#pragma unroll
            for (int r = 0; r < 4; r++) acc[mi][nj][r] = 0.f;

    const int nkt = Keff / 64;   // >= 2 in all uses

    load_stage(0, 0); CP_COMMIT();
    load_stage(1, 1); CP_COMMIT();

    for (int kt = 0; kt < nkt; kt++) {
        CP_WAIT1();
        __syncthreads();
        const uint32_t sA = sb + (kt & 1) * 65536;
        const uint32_t sB = sA + 32768;
#pragma unroll
        for (int ks = 0; ks < 4; ks++) {
            uint32_t af[2][2][4];
#pragma unroll
            for (int mi = 0; mi < 2; mi++) {
                const int row = wm * 32 + mi * 16 + (lane & 15);
                const int k8 = ks * 2 + (lane >> 4);
                const uint32_t off = row * 128 + ((k8 ^ (row & 7)) << 4);
                LDSM4(af[mi][0], sA + off);
                LDSM4(af[mi][1], sA + 16384 + off);
            }
            uint32_t bf[4][2][4];
#pragma unroll
            for (int np = 0; np < 4; np++) {
                const int n = wn * 64 + np * 16 + (lane & 7) + ((lane >> 4) << 3);
                const int k8 = ks * 2 + ((lane >> 3) & 1);
                const uint32_t off = n * 128 + ((k8 ^ (n & 7)) << 4);
                LDSM4(bf[np][0], sB + off);
                LDSM4(bf[np][1], sB + 16384 + off);
            }
#pragma unroll
            for (int mi = 0; mi < 2; mi++)
#pragma unroll
                for (int nj = 0; nj < 8; nj++) {
                    const uint32_t* bh = &bf[nj >> 1][0][(nj & 1) * 2];
                    const uint32_t* bl = &bf[nj >> 1][1][(nj & 1) * 2];
                    MMA16816(acc[mi][nj], af[mi][0], bh[0], bh[1]);
                    MMA16816(acc[mi][nj], af[mi][0], bl[0], bl[1]);
                    MMA16816(acc[mi][nj], af[mi][1], bh[0], bh[1]);
                }
        }
        __syncthreads();
        if (kt + 2 < nkt) load_stage(kt + 2, kt & 1);
        CP_COMMIT();
    }

    // ---- epilogue ----
#pragma unroll
    for (int mi = 0; mi < 2; mi++) {
#pragma unroll
        for (int nj = 0; nj < 8; nj++) {
            const int gr0 = m0 + wm * 32 + mi * 16 + (lane >> 2);
            const int gc  = n0 + wn * 64 + nj * 8 + (lane & 3) * 2;
#pragma unroll
            for (int hf = 0; hf < 2; hf++) {
                const int gr = gr0 + hf * 8;
                const size_t idx = (size_t)gr * ldc + gc;
                float d0 = acc[mi][nj][hf * 2], d1 = acc[mi][nj][hf * 2 + 1];
                if (EPI == 1) { d0 += aux0[gc]; d1 += aux0[gc + 1]; }
                if (EPI == 3) {
                    d0 = gate * amem[idx] + omg * d0;
                    d1 = gate * amem[idx + 1] + omg * d1;
                }
                *(float2*)(Cg + offC + idx) = make_float2(d0, d1);
            }
        }
    }
}

// ===========================================================================
// split / transpose-split kernels
// ===========================================================================
__global__ void split_kernel(const float4* __restrict__ in,
                             uint2* __restrict__ hi, uint2* __restrict__ lo)
{
    const size_t i = (size_t)blockIdx.x * blockDim.x + threadIdx.x;
    const float4 v = in[i];
    const __nv_bfloat16 h0 = __float2bfloat16(v.x), h1 = __float2bfloat16(v.y),
                        h2 = __float2bfloat16(v.z), h3 = __float2bfloat16(v.w);
    const __nv_bfloat16 l0 = __float2bfloat16(v.x - __bfloat162float(h0));
    const __nv_bfloat16 l1 = __float2bfloat16(v.y - __bfloat162float(h1));
    const __nv_bfloat16 l2 = __float2bfloat16(v.z - __bfloat162float(h2));
    const __nv_bfloat16 l3 = __float2bfloat16(v.w - __bfloat162float(h3));
    uint2 uh, ul;
    uh.x = ((uint32_t)__bfloat16_as_ushort(h1) << 16) | __bfloat16_as_ushort(h0);
    uh.y = ((uint32_t)__bfloat16_as_ushort(h3) << 16) | __bfloat16_as_ushort(h2);
    ul.x = ((uint32_t)__bfloat16_as_ushort(l1) << 16) | __bfloat16_as_ushort(l0);
    ul.y = ((uint32_t)__bfloat16_as_ushort(l3) << 16) | __bfloat16_as_ushort(l2);
    hi[i] = uh; lo[i] = ul;
}

// W[K,N] (1024x1024) -> Wt_hi/lo[N,K]
__global__ void splitT_kernel(const float* __restrict__ W,
                              __nv_bfloat16* __restrict__ th, __nv_bfloat16* __restrict__ tl)
{
    __shared__ float t[32][33];
    const int n0 = blockIdx.x * 32, k0 = blockIdx.y * 32;
    const int tx = threadIdx.x, ty = threadIdx.y;
#pragma unroll
    for (int i = 0; i < 4; i++)
        t[ty + i * 8][tx] = W[(size_t)(k0 + ty + i * 8) * CE + n0 + tx];
    __syncthreads();
#pragma unroll
    for (int i = 0; i < 4; i++) {
        const float v = t[tx][ty + i * 8];
        const __nv_bfloat16 h = __float2bfloat16(v);
        const size_t o = (size_t)(n0 + ty + i * 8) * CE + k0 + tx;
        th[o] = h;
        tl[o] = __float2bfloat16(v - __bfloat162float(h));
    }
}

// v [B,S,H,D] head slice -> vt_hi/lo [bh, D, S]
__global__ void vt_split_kernel(const float* __restrict__ v,
                                __nv_bfloat16* __restrict__ th, __nv_bfloat16* __restrict__ tl)
{
    __shared__ float t[32][33];
    const int z = blockIdx.z, b = z / CH, h = z % CH;
    const int s0 = blockIdx.x * 32, d0 = blockIdx.y * 32;
    const int tx = threadIdx.x, ty = threadIdx.y;
#pragma unroll
    for (int i = 0; i < 4; i++)
        t[ty + i * 8][tx] = v[(size_t)(b * CS + s0 + ty + i * 8) * CE + h * CD + d0 + tx];
    __syncthreads();
#pragma unroll
    for (int i = 0; i < 4; i++) {
        const float vv = t[tx][ty + i * 8];
        const __nv_bfloat16 hh = __float2bfloat16(vv);
        const size_t o = ((size_t)z * CD + d0 + ty + i * 8) * CS + s0 + tx;
        th[o] = hh;
        tl[o] = __float2bfloat16(vv - __bfloat162float(hh));
    }
}

// causal softmax over row [0..r]; writes probs as bf16 hi/lo, zeros beyond r
__global__ void softmax_split_kernel(const float* __restrict__ P,
                                     __nv_bfloat16* __restrict__ oh, __nv_bfloat16* __restrict__ ol)
{
    const int z = blockIdx.y;
    const int warp = threadIdx.x >> 5, lane = threadIdx.x & 31;
    const int row = blockIdx.x * 8 + warp;
    const size_t off = (size_t)z * CS * CS + (size_t)row * CS;
    const float* p = P + off;
    __nv_bfloat16* ph = oh + off;
    __nv_bfloat16* pl = ol + off;
    const int len = row + 1;
    float m = -3.0e38f;
    for (int j = lane; j < len; j += 32) m = fmaxf(m, p[j]);
#pragma unroll
    for (int o = 16; o > 0; o >>= 1) m = fmaxf(m, __shfl_xor_sync(0xffffffffu, m, o));
    float sum = 0.f;
    for (int j = lane; j < len; j += 32) sum += __expf(p[j] - m);
#pragma unroll
    for (int o = 16; o > 0; o >>= 1) sum += __shfl_xor_sync(0xffffffffu, sum, o);
    const float inv = 1.f / sum;
    for (int j = lane; j < CS; j += 32) {
        if (j < len) {
            const float w = __expf(p[j] - m) * inv;
            const __nv_bfloat16 h = __float2bfloat16(w);
            ph[j] = h;
            pl[j] = __float2bfloat16(w - __bfloat162float(h));
        } else {
            ph[j] = __float2bfloat16(0.f);
            pl[j] = __float2bfloat16(0.f);
        }
    }
}

// ===========================================================================
// retained fp32 kernels (head-space GEMMs + elementwise)
// ===========================================================================
template <int EPI>
__global__ void __launch_bounds__(256, 2)
sgemm_nn(const float* __restrict__ Ag, const float* __restrict__ Bg,
         float* __restrict__ Cg, int M, int N, int K,
         int lda, int ldb, int ldc,
         const float* __restrict__ aux0, const float* __restrict__ aux1)
{
    const int z = blockIdx.z;
    size_t offA = 0, offB = 0, offC = 0;
    const float* den  = nullptr;
    const float* vsrc = nullptr;
    {
        const int b = z / CH, h = z % CH;
        offA = (size_t)b * CS * CE + (size_t)h * CD;
        offB = (size_t)h * CD * CD;
        offC = offA;
        den  = aux0 + (size_t)z * CS;
        if (EPI == 3) vsrc = aux1 + offA;
    }
    const float* A  = Ag + offA;
    const float* Bm = Bg + offB;
    float*       C  = Cg + offC;

    const int m0 = blockIdx.y * 128;
    const int n0 = blockIdx.x * 128;

    __shared__ __align__(16) float As[8][128];
    __shared__ __align__(16) float Bs[8][128];

    float acc[8][8];
#pragma unroll
    for (int i = 0; i < 8; i++)
#pragma unroll
        for (int j = 0; j < 8; j++) acc[i][j] = 0.f;

    const int tid = threadIdx.x;
    const int a_m = tid >> 1;
    const int a_k = (tid & 1) * 4;
    const int b_k = tid >> 5;
    const int b_n = (tid & 31) * 4;
    const int tx = tid & 15, ty = tid >> 4;

    for (int k0 = 0; k0 < K; k0 += 8) {
        float4 av = *(const float4*)(A + (size_t)(m0 + a_m) * lda + k0 + a_k);
        As[a_k + 0][a_m] = av.x; As[a_k + 1][a_m] = av.y;
        As[a_k + 2][a_m] = av.z; As[a_k + 3][a_m] = av.w;
        *(float4*)(&Bs[b_k][b_n]) =
            *(const float4*)(Bm + (size_t)(k0 + b_k) * ldb + n0 + b_n);
        __syncthreads();
#pragma unroll
        for (int kk = 0; kk < 8; kk++) {
            float a[8], b[8];
            *(float4*)(a)     = *(const float4*)(&As[kk][ty * 4]);
            *(float4*)(a + 4) = *(const float4*)(&As[kk][ty * 4 + 64]);
            *(float4*)(b)     = *(const float4*)(&Bs[kk][tx * 4]);
            *(float4*)(b + 4) = *(const float4*)(&Bs[kk][tx * 4 + 64]);
#pragma unroll
            for (int i = 0; i < 8; i++)
#pragma unroll
                for (int j = 0; j < 8; j++)
                    acc[i][j] = fmaf(a[i], b[j], acc[i][j]);
        }
        __syncthreads();
    }

#pragma unroll
    for (int i = 0; i < 8; i++) {
        const int m = m0 + ty * 4 + (i < 4 ? i : 60 + i);
#pragma unroll
        for (int j = 0; j < 8; j++) {
            const int n = n0 + tx * 4 + (j < 4 ? j : 60 + j);
            const size_t idx = (size_t)m * ldc + n;
            float v = acc[i][j];
            if (EPI == 2)      v = v / (den[m] + 1e-6f);
            else if (EPI == 3) v = vsrc[idx] - v / (den[m] + 1e-6f);
            C[idx] = v;
        }
    }
}

__global__ void __launch_bounds__(256)
sgemm_tn_mem(const float* __restrict__ skg, const float* __restrict__ Ug,
             const float* __restrict__ memg, float* __restrict__ outp)
{
    const int z = blockIdx.z;
    const int b = z / CH, h = z % CH;
    const size_t off = (size_t)b * CS * CE + (size_t)h * CD;
    const float* A  = skg + off;
    const float* Bm = Ug + off;
    const int m0 = blockIdx.y * 64, n0 = blockIdx.x * 64;

    __shared__ __align__(16) float As[16][64];
    __shared__ __align__(16) float Bs[16][64];
    float acc[4][4];
#pragma unroll
    for (int i = 0; i < 4; i++)
#pragma unroll
        for (int j = 0; j < 4; j++) acc[i][j] = 0.f;

    const int tid = threadIdx.x;
    const int lk = tid >> 4;
    const int lm = (tid & 15) * 4;
    const int tx = tid & 15, ty = tid >> 4;

    for (int k0 = 0; k0 < CS; k0 += 16) {
        *(float4*)(&As[lk][lm]) = *(const float4*)(A + (size_t)(k0 + lk) * CE + m0 + lm);
        *(float4*)(&Bs[lk][lm]) = *(const float4*)(Bm + (size_t)(k0 + lk) * CE + n0 + lm);
        __syncthreads();
#pragma unroll
        for (int kk = 0; kk < 16; kk++) {
            float a[4], b[4];
            *(float4*)a = *(const float4*)(&As[kk][ty * 4]);
            *(float4*)b = *(const float4*)(&Bs[kk][tx * 4]);
#pragma unroll
            for (int i = 0; i < 4; i++)
#pragma unroll
                for (int j = 0; j < 4; j++)
                    acc[i][j] = fmaf(a[i], b[j], acc[i][j]);
        }
        __syncthreads();
    }

    const size_t memoff = (size_t)CM * CE;
#pragma unroll
    for (int i = 0; i < 4; i++) {
        const int d = m0 + ty * 4 + i;
#pragma unroll
        for (int j = 0; j < 4; j++) {
            const int e = n0 + tx * 4 + j;
            outp[memoff + ((size_t)z * CD + d) * CD + e] =
                memg[(size_t)h * CD * CD + (size_t)d * CD + e] + acc[i][j];
        }
    }
}

__global__ void sigma_kernel(const float* __restrict__ q, const float* __restrict__ k,
                             float* __restrict__ sq, float* __restrict__ sk)
{
    const size_t i = (size_t)blockIdx.x * blockDim.x + threadIdx.x;
    const float x = q[i];
    sq[i] = (x > 0.f) ? x + 1.f : __expf(x);
    const float y = k[i];
    sk[i] = (y > 0.f) ? y + 1.f : __expf(y);
}

__global__ void denom_kernel(const float* __restrict__ sq, const float* __restrict__ sk,
                             const float* __restrict__ zv,
                             float* __restrict__ denq, float* __restrict__ denk)
{
    const int z = blockIdx.y;
    const int b = z / CH, h = z % CH;
    const int warp = threadIdx.x >> 5, lane = threadIdx.x & 31;
    const int s = blockIdx.x * 8 + warp;
    const size_t base = (size_t)(b * CS + s) * CE + (size_t)h * CD;
    const float* zp = zv + h * CD;
    float aq = 0.f, ak = 0.f;
#pragma unroll
    for (int d = lane; d < CD; d += 32) {
        const float zz = zp[d];
        aq = fmaf(sq[base + d], zz, aq);
        ak = fmaf(sk[base + d], zz, ak);
    }
#pragma unroll
    for (int o = 16; o > 0; o >>= 1) {
        aq += __shfl_xor_sync(0xffffffffu, aq, o);
        ak += __shfl_xor_sync(0xffffffffu, ak, o);
    }
    if (lane == 0) {
        denq[z * CS + s] = aq;
        denk[z * CS + s] = ak;
    }
}

__global__ void znew_kernel(const float* __restrict__ sk, const float* __restrict__ zv,
                            float* __restrict__ outz)
{
    const int z = blockIdx.x;
    const int b = z / CH, h = z % CH;
    const int d = threadIdx.x;
    float sum = zv[h * CD + d];
    const float* p = sk + (size_t)b * CS * CE + (size_t)h * CD + d;
    for (int s = 0; s < CS; s += 8) {
        float t = 0.f;
#pragma unroll
        for (int u = 0; u < 8; u++) t += p[(size_t)(s + u) * CE];
        sum += t;
    }
    outz[(size_t)z * CD + d] = sum;
}

// ===========================================================================
extern "C" void kernel_launch(void* const* d_in, const int* in_sizes, int n_in,
                              void* d_out, int out_size)
{
    (void)in_sizes; (void)n_in; (void)out_size;
    const float* X     = (const float*)d_in[0];
    const float* Wq    = (const float*)d_in[1];
    const float* Wk    = (const float*)d_in[2];
    const float* Wv    = (const float*)d_in[3];
    const float* Wo    = (const float*)d_in[4];
    const float* bo    = (const float*)d_in[5];
    const float* betas = (const float*)d_in[6];
    const float* memp  = (const float*)d_in[7];
    const float* zp    = (const float*)d_in[8];
    float* out = (float*)d_out;

    float *pq, *pk, *pv, *psq, *psk, *pamem, *pU, *pmix, *pP, *pdq, *pdk;
    cudaGetSymbolAddress((void**)&pq,    g_q);
    cudaGetSymbolAddress((void**)&pk,    g_k);
    cudaGetSymbolAddress((void**)&pv,    g_v);
    cudaGetSymbolAddress((void**)&psq,   g_sq);
    cudaGetSymbolAddress((void**)&psk,   g_sk);
    cudaGetSymbolAddress((void**)&pamem, g_amem);
    cudaGetSymbolAddress((void**)&pU,    g_U);
    cudaGetSymbolAddress((void**)&pmix,  g_mix);
    cudaGetSymbolAddress((void**)&pP,    g_P);
    cudaGetSymbolAddress((void**)&pdq,   g_denq);
    cudaGetSymbolAddress((void**)&pdk,   g_denk);

    __nv_bfloat16 *xh, *xl, *qh, *ql, *kh, *kl, *mh, *ml;
    __nv_bfloat16 *wqh, *wql, *wkh, *wkl, *wvh, *wvl, *woh, *wol;
    __nv_bfloat16 *pph, *ppl, *vth, *vtl;
    cudaGetSymbolAddress((void**)&xh,  g_xh);  cudaGetSymbolAddress((void**)&xl,  g_xl);
    cudaGetSymbolAddress((void**)&qh,  g_qh);  cudaGetSymbolAddress((void**)&ql,  g_ql);
    cudaGetSymbolAddress((void**)&kh,  g_kh);  cudaGetSymbolAddress((void**)&kl,  g_kl);
    cudaGetSymbolAddress((void**)&mh,  g_mh);  cudaGetSymbolAddress((void**)&ml,  g_ml);
    cudaGetSymbolAddress((void**)&wqh, g_wqh); cudaGetSymbolAddress((void**)&wql, g_wql);
    cudaGetSymbolAddress((void**)&wkh, g_wkh); cudaGetSymbolAddress((void**)&wkl, g_wkl);
    cudaGetSymbolAddress((void**)&wvh, g_wvh); cudaGetSymbolAddress((void**)&wvl, g_wvl);
    cudaGetSymbolAddress((void**)&woh, g_woh); cudaGetSymbolAddress((void**)&wol, g_wol);
    cudaGetSymbolAddress((void**)&pph, g_ph);  cudaGetSymbolAddress((void**)&ppl, g_pl);
    cudaGetSymbolAddress((void**)&vth, g_vth); cudaGetSymbolAddress((void**)&vtl, g_vtl);

    cudaFuncSetAttribute(hmma_gemm<0>, cudaFuncAttributeMaxDynamicSharedMemorySize, HM_SMEM);
    cudaFuncSetAttribute(hmma_gemm<1>, cudaFuncAttributeMaxDynamicSharedMemorySize, HM_SMEM);
    cudaFuncSetAttribute(hmma_gemm<2>, cudaFuncAttributeMaxDynamicSharedMemorySize, HM_SMEM);
    cudaFuncSetAttribute(hmma_gemm<3>, cudaFuncAttributeMaxDynamicSharedMemorySize, HM_SMEM);

    const dim3 blkT(32, 8);
    const dim3 gSplitBig((unsigned)((size_t)CM * CE / 4 / 256));
    const dim3 gSplitW(CE / 32, CE / 32);
    const dim3 gProj(CE / 128, CM / 128, 1);     // 8 x 64
    const dim3 gQK(CS / 128, CS / 128, CBH);     // 16 x 16 x 16
    const dim3 gPV(CD / 128, CS / 128, CBH);     // 2 x 16 x 16
    const dim3 gHead(CD / 128, CS / 128, CBH);
    const dim3 gMem(CD / 64, CD / 64, CBH);

    // 1) split inputs
    split_kernel<<<gSplitBig, 256>>>((const float4*)X, (uint2*)xh, (uint2*)xl);
    splitT_kernel<<<gSplitW, blkT>>>(Wq, wqh, wql);
    splitT_kernel<<<gSplitW, blkT>>>(Wk, wkh, wkl);
    splitT_kernel<<<gSplitW, blkT>>>(Wv, wvh, wvl);
    splitT_kernel<<<gSplitW, blkT>>>(Wo, woh, wol);

    // 2) projections on HMMA tensor cores
    hmma_gemm<0><<<gProj, 256, HM_SMEM>>>(xh, xl, wqh, wql, pq, CE, CE, CE, CE, nullptr, nullptr);
    hmma_gemm<0><<<gProj, 256, HM_SMEM>>>(xh, xl, wkh, wkl, pk, CE, CE, CE, CE, nullptr, nullptr);
    hmma_gemm<0><<<gProj, 256, HM_SMEM>>>(xh, xl, wvh, wvl, pv, CE, CE, CE, CE, nullptr, nullptr);

    // 3) feature maps + denominators + z_new + A_mem (fp32)
    sigma_kernel<<<(unsigned)((size_t)CM * CE / 256), 256>>>(pq, pk, psq, psk);
    denom_kernel<<<dim3(CS / 8, CBH), 256>>>(psq, psk, zp, pdq, pdk);
    znew_kernel<<<CBH, CD>>>(psk, zp, out + (size_t)CM * CE + (size_t)CBH * CD * CD);
    sgemm_nn<2><<<gHead, 256>>>(psq, memp, pamem, CS, CD, CD, CE, CD, CE, pdq, nullptr);

    // 4) attention: QK^T (hmma) -> softmax(+bf16 split) -> PV (hmma, gate-mix epi)
    split_kernel<<<gSplitBig, 256>>>((const float4*)pq, (uint2*)qh, (uint2*)ql);
    split_kernel<<<gSplitBig, 256>>>((const float4*)pk, (uint2*)kh, (uint2*)kl);
    hmma_gemm<2><<<gQK, 256, HM_SMEM>>>(qh, ql, kh, kl, pP, CD, CE, CE, CS, nullptr, nullptr);
    softmax_split_kernel<<<dim3(CS / 8, CBH), 256>>>(pP, pph, ppl);
    vt_split_kernel<<<dim3(CS / 32, CD / 32, CBH), blkT>>>(pv, vth, vtl);
    hmma_gemm<3><<<gPV, 256, HM_SMEM>>>(pph, ppl, vth, vtl, pmix, CS, CS, CS, CE, pamem, betas);

    // 5) memory update (fp32)
    sgemm_nn<3><<<gHead, 256>>>(psk, memp, pU, CS, CD, CD, CE, CD, CE, pdk, pv);
    sgemm_tn_mem<<<gMem, 256>>>(psk, pU, memp, out);

    // 6) output projection + bias (hmma)
    split_kernel<<<gSplitBig, 256>>>((const float4*)pmix, (uint2*)mh, (uint2*)ml);
    hmma_gemm<1><<<gProj, 256, HM_SMEM>>>(mh, ml, woh, wol, out, CE, CE, CE, CE, bo, nullptr);
}

// round 4
// speedup vs baseline: 2.4660x; 1.1747x over previous
#include <cuda_runtime.h>
#include <cuda_bf16.h>
#include <cstdint>
#include <math.h>

// Problem constants
#define CB 4
#define CS 2048
#define CE 1024
#define CH 4
#define CD 256
#define CBH 16      // B*H
#define CM 8192     // B*S tokens

// ---------------- f32 scratch ----------------
__device__ float g_v   [(size_t)CM * CE];
__device__ float g_sq  [(size_t)CM * CE];
__device__ float g_sk  [(size_t)CM * CE];
__device__ float g_amem[(size_t)CM * CE];
__device__ float g_U   [(size_t)CM * CE];
__device__ float g_P   [(size_t)CBH * CS * CS];   // f32 logits
__device__ float g_denq[CBH * CS];
__device__ float g_denk[CBH * CS];

// ---------------- bf16 scratch (uint4-typed for 16B alignment) ----------------
__device__ uint4 g_xh  [(size_t)CM * CE / 8];
__device__ uint4 g_xl  [(size_t)CM * CE / 8];
__device__ uint4 g_qh  [(size_t)CM * CE / 8];
__device__ uint4 g_ql  [(size_t)CM * CE / 8];
__device__ uint4 g_kh  [(size_t)CM * CE / 8];
__device__ uint4 g_kl  [(size_t)CM * CE / 8];
__device__ uint4 g_mh  [(size_t)CM * CE / 8];   // PV mix split
__device__ uint4 g_ml  [(size_t)CM * CE / 8];
__device__ uint4 g_sqh [(size_t)CM * CE / 8];
__device__ uint4 g_sql [(size_t)CM * CE / 8];
__device__ uint4 g_skh [(size_t)CM * CE / 8];
__device__ uint4 g_skl [(size_t)CM * CE / 8];
__device__ uint4 g_wqh [(size_t)CE * CE / 8];
__device__ uint4 g_wql [(size_t)CE * CE / 8];
__device__ uint4 g_wkh [(size_t)CE * CE / 8];
__device__ uint4 g_wkl [(size_t)CE * CE / 8];
__device__ uint4 g_wvh [(size_t)CE * CE / 8];
__device__ uint4 g_wvl [(size_t)CE * CE / 8];
__device__ uint4 g_woh [(size_t)CE * CE / 8];
__device__ uint4 g_wol [(size_t)CE * CE / 8];
__device__ uint4 g_ph  [(size_t)CBH * CS * CS / 8];  // softmax probs hi
__device__ uint4 g_pl  [(size_t)CBH * CS * CS / 8];  // softmax probs lo
__device__ uint4 g_vth [(size_t)CBH * CD * CS / 8];  // v^T per head
__device__ uint4 g_vtl [(size_t)CBH * CD * CS / 8];
__device__ uint4 g_skth[(size_t)CBH * CD * CS / 8];  // sk^T per head
__device__ uint4 g_sktl[(size_t)CBH * CD * CS / 8];
__device__ uint4 g_uth [(size_t)CBH * CD * CS / 8];  // U^T per head
__device__ uint4 g_utl [(size_t)CBH * CD * CS / 8];
__device__ uint4 g_mth [(size_t)CH * CD * CD / 8];   // mem^T per head
__device__ uint4 g_mtl [(size_t)CH * CD * CD / 8];

// ======================= helpers =======================
__device__ __forceinline__ uint32_t smem_u32(const void* p) {
    uint32_t a;
    asm("{ .reg .u64 t; cvta.to.shared.u64 t, %1; cvt.u32.u64 %0, t; }" : "=r"(a) : "l"(p));
    return a;
}
#define CPA16(dst, src) \
    asm volatile("cp.async.cg.shared.global [%0], [%1], 16;" :: "r"(dst), "l"(src))
#define CP_COMMIT() asm volatile("cp.async.commit_group;")
#define CP_WAIT2()  asm volatile("cp.async.wait_group 2;")

#define LDSM4(r, addr) \
    asm volatile("ldmatrix.sync.aligned.m8n8.x4.shared.b16 {%0,%1,%2,%3}, [%4];" \
        : "=r"((r)[0]), "=r"((r)[1]), "=r"((r)[2]), "=r"((r)[3]) : "r"(addr))

#define MMA16816(d, a, b0, b1) \
    asm volatile("mma.sync.aligned.m16n8k16.row.col.f32.bf16.bf16.f32 " \
        "{%0,%1,%2,%3}, {%4,%5,%6,%7}, {%8,%9}, {%0,%1,%2,%3};" \
        : "+f"((d)[0]), "+f"((d)[1]), "+f"((d)[2]), "+f"((d)[3]) \
        : "r"((a)[0]), "r"((a)[1]), "r"((a)[2]), "r"((a)[3]), "r"(b0), "r"(b1))

__device__ __forceinline__ __nv_bfloat162 split_hi2(float a, float b, __nv_bfloat162& lo) {
    const __nv_bfloat16 h0 = __float2bfloat16(a), h1 = __float2bfloat16(b);
    lo.x = __float2bfloat16(a - __bfloat162float(h0));
    lo.y = __float2bfloat16(b - __bfloat162float(h1));
    __nv_bfloat162 hi; hi.x = h0; hi.y = h1;
    return hi;
}

// ===========================================================================
// HMMA split-bf16 GEMM: C[M,N] = A·B^T. A:[rows,K] K-major lda, B:[cols,K] ldb.
// 3 mma per pair: Ah·Bh + Ah·Bl + Al·Bh. Tile 128x128, KT=64, 3-stage cp.async.
// EPI: 0 f32 | 1 f32+bias | 2 QK causal (skip masked, z=bh) | 3 PV gate-mix ->
//      split out | 4 split out (Q/K proj) | 5 A_mem acc/den | 6 U=v-acc/den |
//      7 mem_new = mem + acc
// ===========================================================================
#define HM_SMEM (3 * 65536 + 1024)

template <int EPI>
__global__ void __launch_bounds__(256, 1)
hmma_gemm(const __nv_bfloat16* __restrict__ Ah, const __nv_bfloat16* __restrict__ Al,
          const __nv_bfloat16* __restrict__ Bh, const __nv_bfloat16* __restrict__ Bl,
          float* __restrict__ Cg, __nv_bfloat16* __restrict__ Oh, __nv_bfloat16* __restrict__ Ol,
          int K, int lda, int ldb, int ldc,
          const float* __restrict__ aux0, const float* __restrict__ aux1)
{
    const int m0 = blockIdx.y * 128, n0 = blockIdx.x * 128;
    const int z = blockIdx.z;
    size_t offA = 0, offB = 0, offC = 0;
    const float* amem = nullptr;
    const float* den  = nullptr;
    const float* vsrc = nullptr;
    const float* msrc = nullptr;
    float gate = 0.f, omg = 0.f;
    int Keff = K;
    if (EPI == 2) {
        if (n0 >= m0 + 128) return;   // fully masked tile: softmax never reads it
        const int b = z / CH, h = z % CH;
        offA = offB = (size_t)b * CS * CE + (size_t)h * CD;
        offC = (size_t)z * CS * CS;
    } else if (EPI == 3) {
        const int b = z / CH, h = z % CH;
        offA = (size_t)z * CS * CS;
        offB = (size_t)z * CD * CS;
        offC = (size_t)b * CS * CE + (size_t)h * CD;
        amem = aux0 + offC;
        gate = 1.f / (1.f + __expf(-aux1[h]));
        omg  = 1.f - gate;
        Keff = min(K, m0 + 128);      // probs zero beyond row block
    } else if (EPI == 5 || EPI == 6) {
        const int b = z / CH, h = z % CH;
        offA = (size_t)b * CS * CE + (size_t)h * CD;
        offB = (size_t)h * CD * CD;
        offC = offA;
        den  = aux0 + (size_t)z * CS;
        if (EPI == 6) vsrc = aux1 + offC;
    } else if (EPI == 7) {
        offA = (size_t)z * CD * CS;
        offB = (size_t)z * CD * CS;
        offC = (size_t)z * CD * CD;
        msrc = aux0 + (size_t)(z % CH) * CD * CD;
    }

    extern __shared__ char dsm_raw[];
    char* base = dsm_raw + ((1024 - (smem_u32(dsm_raw) & 1023)) & 1023);
    const uint32_t sb = smem_u32(base);

    const int tid = threadIdx.x;
    const int wid = tid >> 5, lane = tid & 31;
    const int wm = wid & 3, wn = wid >> 2;

    const __nv_bfloat16* pAh = Ah + offA;
    const __nv_bfloat16* pAl = Al + offA;
    const __nv_bfloat16* pBh = Bh + offB;
    const __nv_bfloat16* pBl = Bl + offB;

    auto load_stage = [&](int kt, int stage) {
        const int k0 = kt * 64;
        const uint32_t sbase = sb + stage * 65536;
#pragma unroll
        for (int it = 0; it < 16; it++) {
            const int mat = it >> 2;
            const int rem = tid + (it & 3) * 256;
            const int row = rem >> 3, k8 = rem & 7;
            const uint32_t dst = sbase + mat * 16384 + row * 128 + ((k8 ^ (row & 7)) << 4);
            const __nv_bfloat16* src;
            if (mat == 0)      src = pAh + (size_t)(m0 + row) * lda + k0 + k8 * 8;
            else if (mat == 1) src = pAl + (size_t)(m0 + row) * lda + k0 + k8 * 8;
            else if (mat == 2) src = pBh + (size_t)(n0 + row) * ldb + k0 + k8 * 8;
            else               src = pBl + (size_t)(n0 + row) * ldb + k0 + k8 * 8;
            CPA16(dst, src);
        }
    };

    float acc[2][8][4];
#pragma unroll
    for (int mi = 0; mi < 2; mi++)
#pragma unroll
        for (int nj = 0; nj < 8; nj++)
#pragma unroll
            for (int r = 0; r < 4; r++) acc[mi][nj][r] = 0.f;

    const int nkt = Keff / 64;   // >= 2 everywhere

    load_stage(0, 0); CP_COMMIT();
    load_stage(1, 1); CP_COMMIT();
    load_stage(2, 2); CP_COMMIT();   // may prefetch past Keff: always in-buffer, unused

    int buf = 0;
    for (int kt = 0; kt < nkt; kt++) {
        CP_WAIT2();
        __syncthreads();
        const uint32_t sA = sb + buf * 65536;
        const uint32_t sB = sA + 32768;
#pragma unroll
        for (int ks = 0; ks < 4; ks++) {
            uint32_t af[2][2][4];
#pragma unroll
            for (int mi = 0; mi < 2; mi++) {
                const int row = wm * 32 + mi * 16 + (lane & 15);
                const int k8 = ks * 2 + (lane >> 4);
                const uint32_t off = row * 128 + ((k8 ^ (row & 7)) << 4);
                LDSM4(af[mi][0], sA + off);
                LDSM4(af[mi][1], sA + 16384 + off);
            }
            uint32_t bf[4][2][4];
#pragma unroll
            for (int np = 0; np < 4; np++) {
                const int n = wn * 64 + np * 16 + (lane & 7) + ((lane >> 4) << 3);
                const int k8 = ks * 2 + ((lane >> 3) & 1);
                const uint32_t off = n * 128 + ((k8 ^ (n & 7)) << 4);
                LDSM4(bf[np][0], sB + off);
                LDSM4(bf[np][1], sB + 16384 + off);
            }
#pragma unroll
            for (int mi = 0; mi < 2; mi++)
#pragma unroll
                for (int nj = 0; nj < 8; nj++) {
                    const uint32_t* bh = &bf[nj >> 1][0][(nj & 1) * 2];
                    const uint32_t* bl = &bf[nj >> 1][1][(nj & 1) * 2];
                    MMA16816(acc[mi][nj], af[mi][0], bh[0], bh[1]);
                    MMA16816(acc[mi][nj], af[mi][0], bl[0], bl[1]);
                    MMA16816(acc[mi][nj], af[mi][1], bh[0], bh[1]);
                }
        }
        __syncthreads();
        if (kt + 3 < nkt) load_stage(kt + 3, buf);
        CP_COMMIT();
        buf = (buf == 2) ? 0 : buf + 1;
    }

    // ---- epilogue ----
#pragma unroll
    for (int mi = 0; mi < 2; mi++) {
#pragma unroll
        for (int nj = 0; nj < 8; nj++) {
            const int gr0 = m0 + wm * 32 + mi * 16 + (lane >> 2);
            const int gc  = n0 + wn * 64 + nj * 8 + (lane & 3) * 2;
#pragma unroll
            for (int hf = 0; hf < 2; hf++) {
                const int gr = gr0 + hf * 8;
                const size_t idx = (size_t)gr * ldc + gc;
                float d0 = acc[mi][nj][hf * 2], d1 = acc[mi][nj][hf * 2 + 1];
                if (EPI == 1) { d0 += aux0[gc]; d1 += aux0[gc + 1]; }
                if (EPI == 3) {
                    d0 = gate * amem[idx] + omg * d0;
                    d1 = gate * amem[idx + 1] + omg * d1;
                }
                if (EPI == 5) {
                    const float r = 1.f / (den[gr] + 1e-6f);
                    d0 *= r; d1 *= r;
                }
                if (EPI == 6) {
                    const float r = 1.f / (den[gr] + 1e-6f);
                    d0 = vsrc[idx] - d0 * r;
                    d1 = vsrc[idx + 1] - d1 * r;
                }
                if (EPI == 7) {
                    d0 += msrc[idx];
                    d1 += msrc[idx + 1];
                }
                if (EPI == 3 || EPI == 4) {
                    __nv_bfloat162 lo;
                    const __nv_bfloat162 hi = split_hi2(d0, d1, lo);
                    *(__nv_bfloat162*)(Oh + offC + idx) = hi;
                    *(__nv_bfloat162*)(Ol + offC + idx) = lo;
                } else {
                    *(float2*)(Cg + offC + idx) = make_float2(d0, d1);
                }
            }
        }
    }
}

// ===========================================================================
// split / transpose-split kernels
// ===========================================================================
__global__ void split_kernel(const float4* __restrict__ in,
                             uint2* __restrict__ hi, uint2* __restrict__ lo)
{
    const size_t i = (size_t)blockIdx.x * blockDim.x + threadIdx.x;
    const float4 v = in[i];
    __nv_bfloat162 l0, l1;
    const __nv_bfloat162 h0 = split_hi2(v.x, v.y, l0);
    const __nv_bfloat162 h1 = split_hi2(v.z, v.w, l1);
    uint2 uh, ul;
    uh.x = *(const uint32_t*)&h0; uh.y = *(const uint32_t*)&h1;
    ul.x = *(const uint32_t*)&l0; ul.y = *(const uint32_t*)&l1;
    hi[i] = uh; lo[i] = ul;
}

// W[K,N] (1024x1024) -> Wt_hi/lo[N,K]
__global__ void splitT_kernel(const float* __restrict__ W,
                              __nv_bfloat16* __restrict__ th, __nv_bfloat16* __restrict__ tl)
{
    __shared__ float t[32][33];
    const int n0 = blockIdx.x * 32, k0 = blockIdx.y * 32;
    const int tx = threadIdx.x, ty = threadIdx.y;
#pragma unroll
    for (int i = 0; i < 4; i++)
        t[ty + i * 8][tx] = W[(size_t)(k0 + ty + i * 8) * CE + n0 + tx];
    __syncthreads();
#pragma unroll
    for (int i = 0; i < 4; i++) {
        const float v = t[tx][ty + i * 8];
        const __nv_bfloat16 h = __float2bfloat16(v);
        const size_t o = (size_t)(n0 + ty + i * 8) * CE + k0 + tx;
        th[o] = h;
        tl[o] = __float2bfloat16(v - __bfloat162float(h));
    }
}

// src [B,S,E] head slice -> dst [bh, D, S] bf16 hi/lo (transpose + split)
__global__ void tsplit_head_kernel(const float* __restrict__ src,
                                   __nv_bfloat16* __restrict__ th, __nv_bfloat16* __restrict__ tl)
{
    __shared__ float t[32][33];
    const int z = blockIdx.z, b = z / CH, h = z % CH;
    const int s0 = blockIdx.x * 32, d0 = blockIdx.y * 32;
    const int tx = threadIdx.x, ty = threadIdx.y;
#pragma unroll
    for (int i = 0; i < 4; i++)
        t[ty + i * 8][tx] = src[(size_t)(b * CS + s0 + ty + i * 8) * CE + h * CD + d0 + tx];
    __syncthreads();
#pragma unroll
    for (int i = 0; i < 4; i++) {
        const float vv = t[tx][ty + i * 8];
        const __nv_bfloat16 hh = __float2bfloat16(vv);
        const size_t o = ((size_t)z * CD + d0 + ty + i * 8) * CS + s0 + tx;
        th[o] = hh;
        tl[o] = __float2bfloat16(vv - __bfloat162float(hh));
    }
}

// mem [H,D,D] -> memT [h, e, d] bf16 hi/lo
__global__ void memT_kernel(const float* __restrict__ mem,
                            __nv_bfloat16* __restrict__ th, __nv_bfloat16* __restrict__ tl)
{
    __shared__ float t[32][33];
    const int h = blockIdx.z;
    const int d0 = blockIdx.x * 32, e0 = blockIdx.y * 32;
    const int tx = threadIdx.x, ty = threadIdx.y;
#pragma unroll
    for (int i = 0; i < 4; i++)
        t[ty + i * 8][tx] = mem[(size_t)h * CD * CD + (size_t)(d0 + ty + i * 8) * CD + e0 + tx];
    __syncthreads();
#pragma unroll
    for (int i = 0; i < 4; i++) {
        const float v = t[tx][ty + i * 8];     // mem[d0+tx][e0+ty+i*8]
        const __nv_bfloat16 hh = __float2bfloat16(v);
        const size_t o = (size_t)h * CD * CD + (size_t)(e0 + ty + i * 8) * CD + d0 + tx;
        th[o] = hh;
        tl[o] = __float2bfloat16(v - __bfloat162float(hh));
    }
}

// sigma from split q/k: s = elu(hi+lo)+1; writes f32 + split bf16
__global__ void sigma2_kernel(const uint2* __restrict__ qh, const uint2* __restrict__ ql,
                              const uint2* __restrict__ kh, const uint2* __restrict__ kl,
                              float4* __restrict__ sqf, float4* __restrict__ skf,
                              uint2* __restrict__ sqh, uint2* __restrict__ sql,
                              uint2* __restrict__ skh, uint2* __restrict__ skl)
{
    const size_t i = (size_t)blockIdx.x * blockDim.x + threadIdx.x;
    auto recon = [](uint2 h, uint2 l, float* o) {
        const __nv_bfloat162 h0 = *(__nv_bfloat162*)&h.x, h1 = *(__nv_bfloat162*)&h.y;
        const __nv_bfloat162 l0 = *(__nv_bfloat162*)&l.x, l1 = *(__nv_bfloat162*)&l.y;
        o[0] = __bfloat162float(h0.x) + __bfloat162float(l0.x);
        o[1] = __bfloat162float(h0.y) + __bfloat162float(l0.y);
        o[2] = __bfloat162float(h1.x) + __bfloat162float(l1.x);
        o[3] = __bfloat162float(h1.y) + __bfloat162float(l1.y);
    };
    auto elu1 = [](float x) { return (x > 0.f) ? x + 1.f : __expf(x); };

    float x[4];
    recon(qh[i], ql[i], x);
#pragma unroll
    for (int j = 0; j < 4; j++) x[j] = elu1(x[j]);
    sqf[i] = make_float4(x[0], x[1], x[2], x[3]);
    {
        __nv_bfloat162 l0, l1;
        const __nv_bfloat162 h0 = split_hi2(x[0], x[1], l0);
        const __nv_bfloat162 h1 = split_hi2(x[2], x[3], l1);
        uint2 uh, ul;
        uh.x = *(const uint32_t*)&h0; uh.y = *(const uint32_t*)&h1;
        ul.x = *(const uint32_t*)&l0; ul.y = *(const uint32_t*)&l1;
        sqh[i] = uh; sql[i] = ul;
    }
    recon(kh[i], kl[i], x);
#pragma unroll
    for (int j = 0; j < 4; j++) x[j] = elu1(x[j]);
    skf[i] = make_float4(x[0], x[1], x[2], x[3]);
    {
        __nv_bfloat162 l0, l1;
        const __nv_bfloat162 h0 = split_hi2(x[0], x[1], l0);
        const __nv_bfloat162 h1 = split_hi2(x[2], x[3], l1);
        uint2 uh, ul;
        uh.x = *(const uint32_t*)&h0; uh.y = *(const uint32_t*)&h1;
        ul.x = *(const uint32_t*)&l0; ul.y = *(const uint32_t*)&l1;
        skh[i] = uh; skl[i] = ul;
    }
}

// denq[bh][s] = sigma_q[row] . z_h ; denk likewise. One warp per row.
__global__ void denom_kernel(const float* __restrict__ sq, const float* __restrict__ sk,
                             const float* __restrict__ zv,
                             float* __restrict__ denq, float* __restrict__ denk)
{
    const int z = blockIdx.y;
    const int b = z / CH, h = z % CH;
    const int warp = threadIdx.x >> 5, lane = threadIdx.x & 31;
    const int s = blockIdx.x * 8 + warp;
    const size_t base = (size_t)(b * CS + s) * CE + (size_t)h * CD;
    const float* zp = zv + h * CD;
    float aq = 0.f, ak = 0.f;
#pragma unroll
    for (int d = lane; d < CD; d += 32) {
        const float zz = zp[d];
        aq = fmaf(sq[base + d], zz, aq);
        ak = fmaf(sk[base + d], zz, ak);
    }
#pragma unroll
    for (int o = 16; o > 0; o >>= 1) {
        aq += __shfl_xor_sync(0xffffffffu, aq, o);
        ak += __shfl_xor_sync(0xffffffffu, ak, o);
    }
    if (lane == 0) {
        denq[z * CS + s] = aq;
        denk[z * CS + s] = ak;
    }
}

// z_new[b,h,d] = z[h,d] + sum_s sigma_k[b,h,s,d]
__global__ void znew_kernel(const float* __restrict__ sk, const float* __restrict__ zv,
                            float* __restrict__ outz)
{
    const int z = blockIdx.x;
    const int b = z / CH, h = z % CH;
    const int d = threadIdx.x;
    float sum = zv[h * CD + d];
    const float* p = sk + (size_t)b * CS * CE + (size_t)h * CD + d;
    for (int s = 0; s < CS; s += 8) {
        float t = 0.f;
#pragma unroll
        for (int u = 0; u < 8; u++) t += p[(size_t)(s + u) * CE];
        sum += t;
    }
    outz[(size_t)z * CD + d] = sum;
}

// causal softmax over row [0..r]; writes probs as bf16 hi/lo, zeros beyond r
__global__ void softmax_split_kernel(const float* __restrict__ P,
                                     __nv_bfloat16* __restrict__ oh, __nv_bfloat16* __restrict__ ol)
{
    const int z = blockIdx.y;
    const int warp = threadIdx.x >> 5, lane = threadIdx.x & 31;
    const int row = blockIdx.x * 8 + warp;
    const size_t off = (size_t)z * CS * CS + (size_t)row * CS;
    const float* p = P + off;
    __nv_bfloat16* ph = oh + off;
    __nv_bfloat16* pl = ol + off;
    const int len = row + 1;
    float m = -3.0e38f;
    for (int j = lane; j < len; j += 32) m = fmaxf(m, p[j]);
#pragma unroll
    for (int o = 16; o > 0; o >>= 1) m = fmaxf(m, __shfl_xor_sync(0xffffffffu, m, o));
    float sum = 0.f;
    for (int j = lane; j < len; j += 32) sum += __expf(p[j] - m);
#pragma unroll
    for (int o = 16; o > 0; o >>= 1) sum += __shfl_xor_sync(0xffffffffu, sum, o);
    const float inv = 1.f / sum;
    for (int j = lane; j < CS; j += 32) {
        if (j < len) {
            const float w = __expf(p[j] - m) * inv;
            const __nv_bfloat16 h = __float2bfloat16(w);
            ph[j] = h;
            pl[j] = __float2bfloat16(w - __bfloat162float(h));
        } else {
            ph[j] = __float2bfloat16(0.f);
            pl[j] = __float2bfloat16(0.f);
        }
    }
}

// ===========================================================================
extern "C" void kernel_launch(void* const* d_in, const int* in_sizes, int n_in,
                              void* d_out, int out_size)
{
    (void)in_sizes; (void)n_in; (void)out_size;
    const float* X     = (const float*)d_in[0];
    const float* Wq    = (const float*)d_in[1];
    const float* Wk    = (const float*)d_in[2];
    const float* Wv    = (const float*)d_in[3];
    const float* Wo    = (const float*)d_in[4];
    const float* bo    = (const float*)d_in[5];
    const float* betas = (const float*)d_in[6];
    const float* memp  = (const float*)d_in[7];
    const float* zp    = (const float*)d_in[8];
    float* out = (float*)d_out;

    float *pv, *psq, *psk, *pamem, *pU, *pP, *pdq, *pdk;
    cudaGetSymbolAddress((void**)&pv,    g_v);
    cudaGetSymbolAddress((void**)&psq,   g_sq);
    cudaGetSymbolAddress((void**)&psk,   g_sk);
    cudaGetSymbolAddress((void**)&pamem, g_amem);
    cudaGetSymbolAddress((void**)&pU,    g_U);
    cudaGetSymbolAddress((void**)&pP,    g_P);
    cudaGetSymbolAddress((void**)&pdq,   g_denq);
    cudaGetSymbolAddress((void**)&pdk,   g_denk);

    __nv_bfloat16 *xh, *xl, *qh, *ql, *kh, *kl, *mh, *ml;
    __nv_bfloat16 *sqh, *sql, *skh, *skl;
    __nv_bfloat16 *wqh, *wql, *wkh, *wkl, *wvh, *wvl, *woh, *wol;
    __nv_bfloat16 *pph, *ppl, *vth, *vtl, *skth, *sktl, *uth, *utl, *mth, *mtl;
    cudaGetSymbolAddress((void**)&xh,   g_xh);   cudaGetSymbolAddress((void**)&xl,   g_xl);
    cudaGetSymbolAddress((void**)&qh,   g_qh);   cudaGetSymbolAddress((void**)&ql,   g_ql);
    cudaGetSymbolAddress((void**)&kh,   g_kh);   cudaGetSymbolAddress((void**)&kl,   g_kl);
    cudaGetSymbolAddress((void**)&mh,   g_mh);   cudaGetSymbolAddress((void**)&ml,   g_ml);
    cudaGetSymbolAddress((void**)&sqh,  g_sqh);  cudaGetSymbolAddress((void**)&sql,  g_sql);
    cudaGetSymbolAddress((void**)&skh,  g_skh);  cudaGetSymbolAddress((void**)&skl,  g_skl);
    cudaGetSymbolAddress((void**)&wqh,  g_wqh);  cudaGetSymbolAddress((void**)&wql,  g_wql);
    cudaGetSymbolAddress((void**)&wkh,  g_wkh);  cudaGetSymbolAddress((void**)&wkl,  g_wkl);
    cudaGetSymbolAddress((void**)&wvh,  g_wvh);  cudaGetSymbolAddress((void**)&wvl,  g_wvl);
    cudaGetSymbolAddress((void**)&woh,  g_woh);  cudaGetSymbolAddress((void**)&wol,  g_wol);
    cudaGetSymbolAddress((void**)&pph,  g_ph);   cudaGetSymbolAddress((void**)&ppl,  g_pl);
    cudaGetSymbolAddress((void**)&vth,  g_vth);  cudaGetSymbolAddress((void**)&vtl,  g_vtl);
    cudaGetSymbolAddress((void**)&skth, g_skth); cudaGetSymbolAddress((void**)&sktl, g_sktl);
    cudaGetSymbolAddress((void**)&uth,  g_uth);  cudaGetSymbolAddress((void**)&utl,  g_utl);
    cudaGetSymbolAddress((void**)&mth,  g_mth);  cudaGetSymbolAddress((void**)&mtl,  g_mtl);

    cudaFuncSetAttribute(hmma_gemm<0>, cudaFuncAttributeMaxDynamicSharedMemorySize, HM_SMEM);
    cudaFuncSetAttribute(hmma_gemm<1>, cudaFuncAttributeMaxDynamicSharedMemorySize, HM_SMEM);
    cudaFuncSetAttribute(hmma_gemm<2>, cudaFuncAttributeMaxDynamicSharedMemorySize, HM_SMEM);
    cudaFuncSetAttribute(hmma_gemm<3>, cudaFuncAttributeMaxDynamicSharedMemorySize, HM_SMEM);
    cudaFuncSetAttribute(hmma_gemm<4>, cudaFuncAttributeMaxDynamicSharedMemorySize, HM_SMEM);
    cudaFuncSetAttribute(hmma_gemm<5>, cudaFuncAttributeMaxDynamicSharedMemorySize, HM_SMEM);
    cudaFuncSetAttribute(hmma_gemm<6>, cudaFuncAttributeMaxDynamicSharedMemorySize, HM_SMEM);
    cudaFuncSetAttribute(hmma_gemm<7>, cudaFuncAttributeMaxDynamicSharedMemorySize, HM_SMEM);

    const dim3 blkT(32, 8);
    const dim3 gSplitBig((unsigned)((size_t)CM * CE / 4 / 256));
    const dim3 gSplitW(CE / 32, CE / 32);
    const dim3 gProj(CE / 128, CM / 128, 1);     // 8 x 64
    const dim3 gQK(CS / 128, CS / 128, CBH);     // 16 x 16 x 16
    const dim3 gPV(CD / 128, CS / 128, CBH);     // 2 x 16 x 16
    const dim3 gAM(CD / 128, CS / 128, CBH);     // 2 x 16 x 16
    const dim3 gMU(CD / 128, CD / 128, CBH);     // 2 x 2 x 16
    const dim3 gTS(CS / 32, CD / 32, CBH);
    const dim3 gMT(CD / 32, CD / 32, CH);
    float* outmem = out + (size_t)CM * CE;
    float* outz   = outmem + (size_t)CBH * CD * CD;

    // 1) split inputs
    split_kernel<<<gSplitBig, 256>>>((const float4*)X, (uint2*)xh, (uint2*)xl);
    splitT_kernel<<<gSplitW, blkT>>>(Wq, wqh, wql);
    splitT_kernel<<<gSplitW, blkT>>>(Wk, wkh, wkl);
    splitT_kernel<<<gSplitW, blkT>>>(Wv, wvh, wvl);
    splitT_kernel<<<gSplitW, blkT>>>(Wo, woh, wol);
    memT_kernel<<<gMT, blkT>>>(memp, mth, mtl);

    // 2) projections (Q/K write split directly; V stays f32)
    hmma_gemm<4><<<gProj, 256, HM_SMEM>>>(xh, xl, wqh, wql, nullptr, qh, ql, CE, CE, CE, CE, nullptr, nullptr);
    hmma_gemm<4><<<gProj, 256, HM_SMEM>>>(xh, xl, wkh, wkl, nullptr, kh, kl, CE, CE, CE, CE, nullptr, nullptr);
    hmma_gemm<0><<<gProj, 256, HM_SMEM>>>(xh, xl, wvh, wvl, pv, nullptr, nullptr, CE, CE, CE, CE, nullptr, nullptr);

    // 3) feature maps + denominators + z_new
    sigma2_kernel<<<gSplitBig, 256>>>((const uint2*)qh, (const uint2*)ql, (const uint2*)kh, (const uint2*)kl,
                                      (float4*)psq, (float4*)psk,
                                      (uint2*)sqh, (uint2*)sql, (uint2*)skh, (uint2*)skl);
    denom_kernel<<<dim3(CS / 8, CBH), 256>>>(psq, psk, zp, pdq, pdk);
    znew_kernel<<<CBH, CD>>>(psk, zp, outz);

    // 4) compressive-memory read: A_mem = (sq @ mem)/(sq.z+1e-6)   [HMMA]
    hmma_gemm<5><<<gAM, 256, HM_SMEM>>>(sqh, sql, mth, mtl, pamem, nullptr, nullptr, CD, CE, CD, CE, pdq, nullptr);

    // 5) causal softmax attention
    hmma_gemm<2><<<gQK, 256, HM_SMEM>>>(qh, ql, kh, kl, pP, nullptr, nullptr, CD, CE, CE, CS, nullptr, nullptr);
    softmax_split_kernel<<<dim3(CS / 8, CBH), 256>>>(pP, pph, ppl);
    tsplit_head_kernel<<<gTS, blkT>>>(pv, vth, vtl);
    hmma_gemm<3><<<gPV, 256, HM_SMEM>>>(pph, ppl, vth, vtl, nullptr, mh, ml, CS, CS, CS, CE, pamem, betas);

    // 6) memory update: U = v - (sk@mem)/(sk.z+1e-6);  mem_new = mem + sk^T U  [HMMA]
    hmma_gemm<6><<<gAM, 256, HM_SMEM>>>(skh, skl, mth, mtl, pU, nullptr, nullptr, CD, CE, CD, CE, pdk, pv);
    tsplit_head_kernel<<<gTS, blkT>>>(psk, skth, sktl);
    tsplit_head_kernel<<<gTS, blkT>>>(pU, uth, utl);
    hmma_gemm<7><<<gMU, 256, HM_SMEM>>>(skth, sktl, uth, utl, outmem, nullptr, nullptr, CS, CS, CS, CD, memp, nullptr);

    // 7) output projection + bias
    hmma_gemm<1><<<gProj, 256, HM_SMEM>>>(mh, ml, woh, wol, out, nullptr, nullptr, CE, CE, CE, CE, bo, nullptr);
}

// round 5
// speedup vs baseline: 2.7789x; 1.1269x over previous
#include <cuda_runtime.h>
#include <cuda_fp16.h>
#include <cstdint>
#include <math.h>

// Problem constants
#define CB 4
#define CS 2048
#define CE 1024
#define CH 4
#define CD 256
#define CBH 16      // B*H
#define CM 8192     // B*S tokens

// ---------------- f32 scratch ----------------
__device__ float g_v   [(size_t)CM * CE];
__device__ float g_sq  [(size_t)CM * CE];
__device__ float g_sk  [(size_t)CM * CE];
__device__ float g_amem[(size_t)CM * CE];
__device__ float g_U   [(size_t)CM * CE];
__device__ float g_P   [(size_t)CBH * CS * CS];   // f32 logits
__device__ float g_denq[CBH * CS];
__device__ float g_denk[CBH * CS];

// ---------------- fp16 scratch (uint4-typed for 16B alignment) ----------------
__device__ uint4 g_xh  [(size_t)CM * CE / 8];
__device__ uint4 g_xl  [(size_t)CM * CE / 8];
__device__ uint4 g_qh  [(size_t)CM * CE / 8];
__device__ uint4 g_ql  [(size_t)CM * CE / 8];
__device__ uint4 g_kh  [(size_t)CM * CE / 8];
__device__ uint4 g_kl  [(size_t)CM * CE / 8];
__device__ uint4 g_mh  [(size_t)CM * CE / 8];   // PV mix split
__device__ uint4 g_ml  [(size_t)CM * CE / 8];
__device__ uint4 g_sqh [(size_t)CM * CE / 8];
__device__ uint4 g_sql [(size_t)CM * CE / 8];
__device__ uint4 g_skh [(size_t)CM * CE / 8];
__device__ uint4 g_skl [(size_t)CM * CE / 8];
__device__ uint4 g_wqh [(size_t)CE * CE / 8];
__device__ uint4 g_wql [(size_t)CE * CE / 8];
__device__ uint4 g_wkh [(size_t)CE * CE / 8];
__device__ uint4 g_wkl [(size_t)CE * CE / 8];
__device__ uint4 g_wvh [(size_t)CE * CE / 8];
__device__ uint4 g_wvl [(size_t)CE * CE / 8];
__device__ uint4 g_woh [(size_t)CE * CE / 8];
__device__ uint4 g_wol [(size_t)CE * CE / 8];
__device__ uint4 g_ph  [(size_t)CBH * CS * CS / 8];  // softmax probs hi
__device__ uint4 g_pl  [(size_t)CBH * CS * CS / 8];  // softmax probs lo
__device__ uint4 g_vth [(size_t)CBH * CD * CS / 8];  // v^T per head
__device__ uint4 g_vtl [(size_t)CBH * CD * CS / 8];
__device__ uint4 g_skth[(size_t)CBH * CD * CS / 8];  // sk^T per head
__device__ uint4 g_sktl[(size_t)CBH * CD * CS / 8];
__device__ uint4 g_uth [(size_t)CBH * CD * CS / 8];  // U^T per head
__device__ uint4 g_utl [(size_t)CBH * CD * CS / 8];
__device__ uint4 g_mth [(size_t)CH * CD * CD / 8];   // mem^T per head
__device__ uint4 g_mtl [(size_t)CH * CD * CD / 8];

// ======================= helpers =======================
__device__ __forceinline__ uint32_t smem_u32(const void* p) {
    uint32_t a;
    asm("{ .reg .u64 t; cvta.to.shared.u64 t, %1; cvt.u32.u64 %0, t; }" : "=r"(a) : "l"(p));
    return a;
}
#define CPA16(dst, src) \
    asm volatile("cp.async.cg.shared.global [%0], [%1], 16;" :: "r"(dst), "l"(src))
#define CP_COMMIT() asm volatile("cp.async.commit_group;")
#define CP_WAIT2()  asm volatile("cp.async.wait_group 2;")

#define LDSM4(r, addr) \
    asm volatile("ldmatrix.sync.aligned.m8n8.x4.shared.b16 {%0,%1,%2,%3}, [%4];" \
        : "=r"((r)[0]), "=r"((r)[1]), "=r"((r)[2]), "=r"((r)[3]) : "r"(addr))

#define MMA16816(d, a, b0, b1) \
    asm volatile("mma.sync.aligned.m16n8k16.row.col.f32.f16.f16.f32 " \
        "{%0,%1,%2,%3}, {%4,%5,%6,%7}, {%8,%9}, {%0,%1,%2,%3};" \
        : "+f"((d)[0]), "+f"((d)[1]), "+f"((d)[2]), "+f"((d)[3]) \
        : "r"((a)[0]), "r"((a)[1]), "r"((a)[2]), "r"((a)[3]), "r"(b0), "r"(b1))

__device__ __forceinline__ __half2 split_hi2(float a, float b, __half2& lo) {
    const __half h0 = __float2half_rn(a), h1 = __float2half_rn(b);
    lo = __halves2half2(__float2half_rn(a - __half2float(h0)),
                        __float2half_rn(b - __half2float(h1)));
    return __halves2half2(h0, h1);
}

// ===========================================================================
// HMMA split-fp16 GEMM: C[M,N] = A·B^T. A:[rows,K] K-major lda, B:[cols,K] ldb.
// NTERM=3: Ah·Bh + Ah·Bl + Al·Bh. NTERM=2: Ah·Bh + Al·Bh (B hi-only).
// Tile 128x128, KT=64, 3-stage cp.async. 8 warps (4M x 2N).
// EPI: 0 f32 | 1 f32+bias | 2 QK causal (skip masked, z=bh) | 3 PV gate-mix ->
//      split out | 4 split out (Q/K proj) | 5 A_mem acc/den | 6 U=v-acc/den |
//      7 mem_new = mem + acc
// ===========================================================================
#define HM_SMEM3 (3 * 65536 + 1024)
#define HM_SMEM2 (3 * 49152 + 1024)

template <int EPI, int NTERM>
__global__ void __launch_bounds__(256, 1)
hmma_gemm(const __half* __restrict__ Ah, const __half* __restrict__ Al,
          const __half* __restrict__ Bh, const __half* __restrict__ Bl,
          float* __restrict__ Cg, __half* __restrict__ Oh, __half* __restrict__ Ol,
          int K, int lda, int ldb, int ldc,
          const float* __restrict__ aux0, const float* __restrict__ aux1)
{
    const int m0 = blockIdx.y * 128, n0 = blockIdx.x * 128;
    const int z = blockIdx.z;
    constexpr int SS = (NTERM == 3) ? 65536 : 49152;   // stage stride
    size_t offA = 0, offB = 0, offC = 0;
    const float* amem = nullptr;
    const float* den  = nullptr;
    const float* vsrc = nullptr;
    const float* msrc = nullptr;
    float gate = 0.f, omg = 0.f;
    int Keff = K;
    if (EPI == 2) {
        if (n0 >= m0 + 128) return;   // fully masked tile: softmax never reads it
        const int b = z / CH, h = z % CH;
        offA = offB = (size_t)b * CS * CE + (size_t)h * CD;
        offC = (size_t)z * CS * CS;
    } else if (EPI == 3) {
        const int b = z / CH, h = z % CH;
        offA = (size_t)z * CS * CS;
        offB = (size_t)z * CD * CS;
        offC = (size_t)b * CS * CE + (size_t)h * CD;
        amem = aux0 + offC;
        gate = 1.f / (1.f + __expf(-aux1[h]));
        omg  = 1.f - gate;
        Keff = min(K, m0 + 128);      // probs zero beyond row block
    } else if (EPI == 5 || EPI == 6) {
        const int b = z / CH, h = z % CH;
        offA = (size_t)b * CS * CE + (size_t)h * CD;
        offB = (size_t)h * CD * CD;
        offC = offA;
        den  = aux0 + (size_t)z * CS;
        if (EPI == 6) vsrc = aux1 + offC;
    } else if (EPI == 7) {
        offA = (size_t)z * CD * CS;
        offB = (size_t)z * CD * CS;
        offC = (size_t)z * CD * CD;
        msrc = aux0 + (size_t)(z % CH) * CD * CD;
    }

    extern __shared__ char dsm_raw[];
    char* base = dsm_raw + ((1024 - (smem_u32(dsm_raw) & 1023)) & 1023);
    const uint32_t sb = smem_u32(base);

    const int tid = threadIdx.x;
    const int wid = tid >> 5, lane = tid & 31;
    const int wm = wid & 3, wn = wid >> 2;

    const __half* pAh = Ah + offA;
    const __half* pAl = Al + offA;
    const __half* pBh = Bh + offB;
    const __half* pBl = Bl + offB;

    auto load_stage = [&](int kt, int stage) {
        const int k0 = kt * 64;
        const uint32_t sbase = sb + stage * SS;
        constexpr int NIT = (NTERM == 3) ? 16 : 12;
#pragma unroll
        for (int it = 0; it < NIT; it++) {
            const int mat = it >> 2;
            const int rem = tid + (it & 3) * 256;
            const int row = rem >> 3, k8 = rem & 7;
            const uint32_t dst = sbase + mat * 16384 + row * 128 + ((k8 ^ (row & 7)) << 4);
            const __half* src;
            if (mat == 0)      src = pAh + (size_t)(m0 + row) * lda + k0 + k8 * 8;
            else if (mat == 1) src = pAl + (size_t)(m0 + row) * lda + k0 + k8 * 8;
            else if (mat == 2) src = pBh + (size_t)(n0 + row) * ldb + k0 + k8 * 8;
            else               src = pBl + (size_t)(n0 + row) * ldb + k0 + k8 * 8;
            CPA16(dst, src);
        }
    };

    float acc[2][8][4];
#pragma unroll
    for (int mi = 0; mi < 2; mi++)
#pragma unroll
        for (int nj = 0; nj < 8; nj++)
#pragma unroll
            for (int r = 0; r < 4; r++) acc[mi][nj][r] = 0.f;

    const int nkt = Keff / 64;   // >= 2 everywhere

    load_stage(0, 0); CP_COMMIT();
    load_stage(1, 1); CP_COMMIT();
    load_stage(2, 2); CP_COMMIT();   // may prefetch past Keff: in-bounds, unused

    int buf = 0;
    for (int kt = 0; kt < nkt; kt++) {
        CP_WAIT2();
        __syncthreads();
        const uint32_t sA = sb + buf * SS;
        const uint32_t sB = sA + 32768;
#pragma unroll
        for (int ks = 0; ks < 4; ks++) {
            uint32_t af[2][2][4];
#pragma unroll
            for (int mi = 0; mi < 2; mi++) {
                const int row = wm * 32 + mi * 16 + (lane & 15);
                const int k8 = ks * 2 + (lane >> 4);
                const uint32_t off = row * 128 + ((k8 ^ (row & 7)) << 4);
                LDSM4(af[mi][0], sA + off);
                LDSM4(af[mi][1], sA + 16384 + off);
            }
            uint32_t bf[4][2][4];
#pragma unroll
            for (int np = 0; np < 4; np++) {
                const int n = wn * 64 + np * 16 + (lane & 7) + ((lane >> 4) << 3);
                const int k8 = ks * 2 + ((lane >> 3) & 1);
                const uint32_t off = n * 128 + ((k8 ^ (n & 7)) << 4);
                LDSM4(bf[np][0], sB + off);
                if (NTERM == 3) LDSM4(bf[np][1], sB + 16384 + off);
            }
#pragma unroll
            for (int mi = 0; mi < 2; mi++)
#pragma unroll
                for (int nj = 0; nj < 8; nj++) {
                    const uint32_t* bh = &bf[nj >> 1][0][(nj & 1) * 2];
                    MMA16816(acc[mi][nj], af[mi][0], bh[0], bh[1]);
                    if (NTERM == 3) {
                        const uint32_t* bl = &bf[nj >> 1][1][(nj & 1) * 2];
                        MMA16816(acc[mi][nj], af[mi][0], bl[0], bl[1]);
                    }
                    MMA16816(acc[mi][nj], af[mi][1], bh[0], bh[1]);
                }
        }
        __syncthreads();
        if (kt + 3 < nkt) load_stage(kt + 3, buf);
        CP_COMMIT();
        buf = (buf == 2) ? 0 : buf + 1;
    }

    // ---- epilogue ----
#pragma unroll
    for (int mi = 0; mi < 2; mi++) {
#pragma unroll
        for (int nj = 0; nj < 8; nj++) {
            const int gr0 = m0 + wm * 32 + mi * 16 + (lane >> 2);
            const int gc  = n0 + wn * 64 + nj * 8 + (lane & 3) * 2;
#pragma unroll
            for (int hf = 0; hf < 2; hf++) {
                const int gr = gr0 + hf * 8;
                const size_t idx = (size_t)gr * ldc + gc;
                float d0 = acc[mi][nj][hf * 2], d1 = acc[mi][nj][hf * 2 + 1];
                if (EPI == 1) { d0 += aux0[gc]; d1 += aux0[gc + 1]; }
                if (EPI == 3) {
                    d0 = gate * amem[idx] + omg * d0;
                    d1 = gate * amem[idx + 1] + omg * d1;
                }
                if (EPI == 5) {
                    const float r = 1.f / (den[gr] + 1e-6f);
                    d0 *= r; d1 *= r;
                }
                if (EPI == 6) {
                    const float r = 1.f / (den[gr] + 1e-6f);
                    d0 = vsrc[idx] - d0 * r;
                    d1 = vsrc[idx + 1] - d1 * r;
                }
                if (EPI == 7) {
                    d0 += msrc[idx];
                    d1 += msrc[idx + 1];
                }
                if (EPI == 3 || EPI == 4) {
                    __half2 lo;
                    const __half2 hi = split_hi2(d0, d1, lo);
                    *(__half2*)(Oh + offC + idx) = hi;
                    *(__half2*)(Ol + offC + idx) = lo;
                } else {
                    *(float2*)(Cg + offC + idx) = make_float2(d0, d1);
                }
            }
        }
    }
}

// ===========================================================================
// split / transpose-split kernels
// ===========================================================================
__global__ void split_kernel(const float4* __restrict__ in,
                             uint2* __restrict__ hi, uint2* __restrict__ lo)
{
    const size_t i = (size_t)blockIdx.x * blockDim.x + threadIdx.x;
    const float4 v = in[i];
    __half2 l0, l1;
    const __half2 h0 = split_hi2(v.x, v.y, l0);
    const __half2 h1 = split_hi2(v.z, v.w, l1);
    uint2 uh, ul;
    uh.x = *(const uint32_t*)&h0; uh.y = *(const uint32_t*)&h1;
    ul.x = *(const uint32_t*)&l0; ul.y = *(const uint32_t*)&l1;
    hi[i] = uh; lo[i] = ul;
}

// W[K,N] (1024x1024) -> Wt_hi/lo[N,K]
__global__ void splitT_kernel(const float* __restrict__ W,
                              __half* __restrict__ th, __half* __restrict__ tl)
{
    __shared__ float t[32][33];
    const int n0 = blockIdx.x * 32, k0 = blockIdx.y * 32;
    const int tx = threadIdx.x, ty = threadIdx.y;
#pragma unroll
    for (int i = 0; i < 4; i++)
        t[ty + i * 8][tx] = W[(size_t)(k0 + ty + i * 8) * CE + n0 + tx];
    __syncthreads();
#pragma unroll
    for (int i = 0; i < 4; i++) {
        const float v = t[tx][ty + i * 8];
        const __half h = __float2half_rn(v);
        const size_t o = (size_t)(n0 + ty + i * 8) * CE + k0 + tx;
        th[o] = h;
        tl[o] = __float2half_rn(v - __half2float(h));
    }
}

// src [B,S,E] head slice -> dst [bh, D, S] fp16 hi/lo (transpose + split)
__global__ void tsplit_head_kernel(const float* __restrict__ src,
                                   __half* __restrict__ th, __half* __restrict__ tl)
{
    __shared__ float t[32][33];
    const int z = blockIdx.z, b = z / CH, h = z % CH;
    const int s0 = blockIdx.x * 32, d0 = blockIdx.y * 32;
    const int tx = threadIdx.x, ty = threadIdx.y;
#pragma unroll
    for (int i = 0; i < 4; i++)
        t[ty + i * 8][tx] = src[(size_t)(b * CS + s0 + ty + i * 8) * CE + h * CD + d0 + tx];
    __syncthreads();
#pragma unroll
    for (int i = 0; i < 4; i++) {
        const float vv = t[tx][ty + i * 8];
        const __half hh = __float2half_rn(vv);
        const size_t o = ((size_t)z * CD + d0 + ty + i * 8) * CS + s0 + tx;
        th[o] = hh;
        tl[o] = __float2half_rn(vv - __half2float(hh));
    }
}

// mem [H,D,D] -> memT [h, e, d] fp16 hi/lo
__global__ void memT_kernel(const float* __restrict__ mem,
                            __half* __restrict__ th, __half* __restrict__ tl)
{
    __shared__ float t[32][33];
    const int h = blockIdx.z;
    const int d0 = blockIdx.x * 32, e0 = blockIdx.y * 32;
    const int tx = threadIdx.x, ty = threadIdx.y;
#pragma unroll
    for (int i = 0; i < 4; i++)
        t[ty + i * 8][tx] = mem[(size_t)h * CD * CD + (size_t)(d0 + ty + i * 8) * CD + e0 + tx];
    __syncthreads();
#pragma unroll
    for (int i = 0; i < 4; i++) {
        const float v = t[tx][ty + i * 8];     // mem[d0+tx][e0+ty+i*8]
        const __half hh = __float2half_rn(v);
        const size_t o = (size_t)h * CD * CD + (size_t)(e0 + ty + i * 8) * CD + d0 + tx;
        th[o] = hh;
        tl[o] = __float2half_rn(v - __half2float(hh));
    }
}

// sigma from split q/k: s = elu(hi+lo)+1; writes f32 + split fp16
__global__ void sigma2_kernel(const uint2* __restrict__ qh, const uint2* __restrict__ ql,
                              const uint2* __restrict__ kh, const uint2* __restrict__ kl,
                              float4* __restrict__ sqf, float4* __restrict__ skf,
                              uint2* __restrict__ sqh, uint2* __restrict__ sql,
                              uint2* __restrict__ skh, uint2* __restrict__ skl)
{
    const size_t i = (size_t)blockIdx.x * blockDim.x + threadIdx.x;
    auto recon = [](uint2 h, uint2 l, float* o) {
        const __half2 h0 = *(__half2*)&h.x, h1 = *(__half2*)&h.y;
        const __half2 l0 = *(__half2*)&l.x, l1 = *(__half2*)&l.y;
        o[0] = __half2float(h0.x) + __half2float(l0.x);
        o[1] = __half2float(h0.y) + __half2float(l0.y);
        o[2] = __half2float(h1.x) + __half2float(l1.x);
        o[3] = __half2float(h1.y) + __half2float(l1.y);
    };
    auto elu1 = [](float x) { return (x > 0.f) ? x + 1.f : __expf(x); };

    float x[4];
    recon(qh[i], ql[i], x);
#pragma unroll
    for (int j = 0; j < 4; j++) x[j] = elu1(x[j]);
    sqf[i] = make_float4(x[0], x[1], x[2], x[3]);
    {
        __half2 l0, l1;
        const __half2 h0 = split_hi2(x[0], x[1], l0);
        const __half2 h1 = split_hi2(x[2], x[3], l1);
        uint2 uh, ul;
        uh.x = *(const uint32_t*)&h0; uh.y = *(const uint32_t*)&h1;
        ul.x = *(const uint32_t*)&l0; ul.y = *(const uint32_t*)&l1;
        sqh[i] = uh; sql[i] = ul;
    }
    recon(kh[i], kl[i], x);
#pragma unroll
    for (int j = 0; j < 4; j++) x[j] = elu1(x[j]);
    skf[i] = make_float4(x[0], x[1], x[2], x[3]);
    {
        __half2 l0, l1;
        const __half2 h0 = split_hi2(x[0], x[1], l0);
        const __half2 h1 = split_hi2(x[2], x[3], l1);
        uint2 uh, ul;
        uh.x = *(const uint32_t*)&h0; uh.y = *(const uint32_t*)&h1;
        ul.x = *(const uint32_t*)&l0; ul.y = *(const uint32_t*)&l1;
        skh[i] = uh; skl[i] = ul;
    }
}

// denq[bh][s] = sigma_q[row] . z_h ; denk likewise. One warp per row.
__global__ void denom_kernel(const float* __restrict__ sq, const float* __restrict__ sk,
                             const float* __restrict__ zv,
                             float* __restrict__ denq, float* __restrict__ denk)
{
    const int z = blockIdx.y;
    const int b = z / CH, h = z % CH;
    const int warp = threadIdx.x >> 5, lane = threadIdx.x & 31;
    const int s = blockIdx.x * 8 + warp;
    const size_t base = (size_t)(b * CS + s) * CE + (size_t)h * CD;
    const float* zp = zv + h * CD;
    float aq = 0.f, ak = 0.f;
#pragma unroll
    for (int d = lane; d < CD; d += 32) {
        const float zz = zp[d];
        aq = fmaf(sq[base + d], zz, aq);
        ak = fmaf(sk[base + d], zz, ak);
    }
#pragma unroll
    for (int o = 16; o > 0; o >>= 1) {
        aq += __shfl_xor_sync(0xffffffffu, aq, o);
        ak += __shfl_xor_sync(0xffffffffu, ak, o);
    }
    if (lane == 0) {
        denq[z * CS + s] = aq;
        denk[z * CS + s] = ak;
    }
}

// z_new[b,h,d] = z[h,d] + sum_s sigma_k[b,h,s,d]
__global__ void znew_kernel(const float* __restrict__ sk, const float* __restrict__ zv,
                            float* __restrict__ outz)
{
    const int z = blockIdx.x;
    const int b = z / CH, h = z % CH;
    const int d = threadIdx.x;
    float sum = zv[h * CD + d];
    const float* p = sk + (size_t)b * CS * CE + (size_t)h * CD + d;
    for (int s = 0; s < CS; s += 8) {
        float t = 0.f;
#pragma unroll
        for (int u = 0; u < 8; u++) t += p[(size_t)(s + u) * CE];
        sum += t;
    }
    outz[(size_t)z * CD + d] = sum;
}

// register-resident causal softmax: one warp per row, single exp, single read
__global__ void __launch_bounds__(256)
softmax_reg_kernel(const float* __restrict__ P,
                   __half* __restrict__ oh, __half* __restrict__ ol)
{
    const int z = blockIdx.y;
    const int warp = threadIdx.x >> 5, lane = threadIdx.x & 31;
    const int row = blockIdx.x * 8 + warp;
    const size_t off = (size_t)z * CS * CS + (size_t)row * CS;
    const float4* p4 = (const float4*)(P + off);
    const int len = row + 1;

    float v[64];
#pragma unroll
    for (int i = 0; i < 16; i++)
        *(float4*)(v + i * 4) = p4[i * 32 + lane];

    float m = -3.0e38f;
#pragma unroll
    for (int i = 0; i < 16; i++) {
        const int c = i * 128 + lane * 4;
#pragma unroll
        for (int j = 0; j < 4; j++) {
            if (c + j >= len) v[i * 4 + j] = -3.0e38f;
            m = fmaxf(m, v[i * 4 + j]);
        }
    }
#pragma unroll
    for (int o = 16; o > 0; o >>= 1) m = fmaxf(m, __shfl_xor_sync(0xffffffffu, m, o));

    float sum = 0.f;
#pragma unroll
    for (int i = 0; i < 64; i++) {
        v[i] = __expf(v[i] - m);       // masked -> exp(-huge) = 0
        sum += v[i];
    }
#pragma unroll
    for (int o = 16; o > 0; o >>= 1) sum += __shfl_xor_sync(0xffffffffu, sum, o);
    const float inv = 1.f / sum;

    __half* ph = oh + off;
    __half* pl = ol + off;
#pragma unroll
    for (int i = 0; i < 16; i++) {
        const int c = i * 128 + lane * 4;
        __half2 l0, l1;
        const __half2 h0 = split_hi2(v[i * 4] * inv, v[i * 4 + 1] * inv, l0);
        const __half2 h1 = split_hi2(v[i * 4 + 2] * inv, v[i * 4 + 3] * inv, l1);
        uint2 uh, ul;
        uh.x = *(const uint32_t*)&h0; uh.y = *(const uint32_t*)&h1;
        ul.x = *(const uint32_t*)&l0; ul.y = *(const uint32_t*)&l1;
        *(uint2*)(ph + c) = uh;
        *(uint2*)(pl + c) = ul;
    }
}

// ===========================================================================
extern "C" void kernel_launch(void* const* d_in, const int* in_sizes, int n_in,
                              void* d_out, int out_size)
{
    (void)in_sizes; (void)n_in; (void)out_size;
    const float* X     = (const float*)d_in[0];
    const float* Wq    = (const float*)d_in[1];
    const float* Wk    = (const float*)d_in[2];
    const float* Wv    = (const float*)d_in[3];
    const float* Wo    = (const float*)d_in[4];
    const float* bo    = (const float*)d_in[5];
    const float* betas = (const float*)d_in[6];
    const float* memp  = (const float*)d_in[7];
    const float* zp    = (const float*)d_in[8];
    float* out = (float*)d_out;

    float *pv, *psq, *psk, *pamem, *pU, *pP, *pdq, *pdk;
    cudaGetSymbolAddress((void**)&pv,    g_v);
    cudaGetSymbolAddress((void**)&psq,   g_sq);
    cudaGetSymbolAddress((void**)&psk,   g_sk);
    cudaGetSymbolAddress((void**)&pamem, g_amem);
    cudaGetSymbolAddress((void**)&pU,    g_U);
    cudaGetSymbolAddress((void**)&pP,    g_P);
    cudaGetSymbolAddress((void**)&pdq,   g_denq);
    cudaGetSymbolAddress((void**)&pdk,   g_denk);

    __half *xh, *xl, *qh, *ql, *kh, *kl, *mh, *ml;
    __half *sqh, *sql, *skh, *skl;
    __half *wqh, *wql, *wkh, *wkl, *wvh, *wvl, *woh, *wol;
    __half *pph, *ppl, *vth, *vtl, *skth, *sktl, *uth, *utl, *mth, *mtl;
    cudaGetSymbolAddress((void**)&xh,   g_xh);   cudaGetSymbolAddress((void**)&xl,   g_xl);
    cudaGetSymbolAddress((void**)&qh,   g_qh);   cudaGetSymbolAddress((void**)&ql,   g_ql);
    cudaGetSymbolAddress((void**)&kh,   g_kh);   cudaGetSymbolAddress((void**)&kl,   g_kl);
    cudaGetSymbolAddress((void**)&mh,   g_mh);   cudaGetSymbolAddress((void**)&ml,   g_ml);
    cudaGetSymbolAddress((void**)&sqh,  g_sqh);  cudaGetSymbolAddress((void**)&sql,  g_sql);
    cudaGetSymbolAddress((void**)&skh,  g_skh);  cudaGetSymbolAddress((void**)&skl,  g_skl);
    cudaGetSymbolAddress((void**)&wqh,  g_wqh);  cudaGetSymbolAddress((void**)&wql,  g_wql);
    cudaGetSymbolAddress((void**)&wkh,  g_wkh);  cudaGetSymbolAddress((void**)&wkl,  g_wkl);
    cudaGetSymbolAddress((void**)&wvh,  g_wvh);  cudaGetSymbolAddress((void**)&wvl,  g_wvl);
    cudaGetSymbolAddress((void**)&woh,  g_woh);  cudaGetSymbolAddress((void**)&wol,  g_wol);
    cudaGetSymbolAddress((void**)&pph,  g_ph);   cudaGetSymbolAddress((void**)&ppl,  g_pl);
    cudaGetSymbolAddress((void**)&vth,  g_vth);  cudaGetSymbolAddress((void**)&vtl,  g_vtl);
    cudaGetSymbolAddress((void**)&skth, g_skth); cudaGetSymbolAddress((void**)&sktl, g_sktl);
    cudaGetSymbolAddress((void**)&uth,  g_uth);  cudaGetSymbolAddress((void**)&utl,  g_utl);
    cudaGetSymbolAddress((void**)&mth,  g_mth);  cudaGetSymbolAddress((void**)&mtl,  g_mtl);

    cudaFuncSetAttribute(hmma_gemm<4,3>, cudaFuncAttributeMaxDynamicSharedMemorySize, HM_SMEM3);
    cudaFuncSetAttribute(hmma_gemm<2,3>, cudaFuncAttributeMaxDynamicSharedMemorySize, HM_SMEM3);
    cudaFuncSetAttribute(hmma_gemm<7,3>, cudaFuncAttributeMaxDynamicSharedMemorySize, HM_SMEM3);
    cudaFuncSetAttribute(hmma_gemm<0,2>, cudaFuncAttributeMaxDynamicSharedMemorySize, HM_SMEM2);
    cudaFuncSetAttribute(hmma_gemm<1,2>, cudaFuncAttributeMaxDynamicSharedMemorySize, HM_SMEM2);
    cudaFuncSetAttribute(hmma_gemm<3,2>, cudaFuncAttributeMaxDynamicSharedMemorySize, HM_SMEM2);
    cudaFuncSetAttribute(hmma_gemm<5,2>, cudaFuncAttributeMaxDynamicSharedMemorySize, HM_SMEM2);
    cudaFuncSetAttribute(hmma_gemm<6,2>, cudaFuncAttributeMaxDynamicSharedMemorySize, HM_SMEM2);

    const dim3 blkT(32, 8);
    const dim3 gSplitBig((unsigned)((size_t)CM * CE / 4 / 256));
    const dim3 gSplitW(CE / 32, CE / 32);
    const dim3 gProj(CE / 128, CM / 128, 1);     // 8 x 64
    const dim3 gQK(CS / 128, CS / 128, CBH);     // 16 x 16 x 16
    const dim3 gPV(CD / 128, CS / 128, CBH);     // 2 x 16 x 16
    const dim3 gAM(CD / 128, CS / 128, CBH);     // 2 x 16 x 16
    const dim3 gMU(CD / 128, CD / 128, CBH);     // 2 x 2 x 16
    const dim3 gTS(CS / 32, CD / 32, CBH);
    const dim3 gMT(CD / 32, CD / 32, CH);
    float* outmem = out + (size_t)CM * CE;
    float* outz   = outmem + (size_t)CBH * CD * CD;

    // 1) split inputs
    split_kernel<<<gSplitBig, 256>>>((const float4*)X, (uint2*)xh, (uint2*)xl);
    splitT_kernel<<<gSplitW, blkT>>>(Wq, wqh, wql);
    splitT_kernel<<<gSplitW, blkT>>>(Wk, wkh, wkl);
    splitT_kernel<<<gSplitW, blkT>>>(Wv, wvh, wvl);
    splitT_kernel<<<gSplitW, blkT>>>(Wo, woh, wol);
    memT_kernel<<<gMT, blkT>>>(memp, mth, mtl);

    // 2) projections (Q/K 3-term, split out; V 2-term f32 out)
    hmma_gemm<4,3><<<gProj, 256, HM_SMEM3>>>(xh, xl, wqh, wql, nullptr, qh, ql, CE, CE, CE, CE, nullptr, nullptr);
    hmma_gemm<4,3><<<gProj, 256, HM_SMEM3>>>(xh, xl, wkh, wkl, nullptr, kh, kl, CE, CE, CE, CE, nullptr, nullptr);
    hmma_gemm<0,2><<<gProj, 256, HM_SMEM2>>>(xh, xl, wvh, wvl, pv, nullptr, nullptr, CE, CE, CE, CE, nullptr, nullptr);

    // 3) feature maps + denominators + z_new
    sigma2_kernel<<<gSplitBig, 256>>>((const uint2*)qh, (const uint2*)ql, (const uint2*)kh, (const uint2*)kl,
                                      (float4*)psq, (float4*)psk,
                                      (uint2*)sqh, (uint2*)sql, (uint2*)skh, (uint2*)skl);
    denom_kernel<<<dim3(CS / 8, CBH), 256>>>(psq, psk, zp, pdq, pdk);
    znew_kernel<<<CBH, CD>>>(psk, zp, outz);

    // 4) compressive-memory read: A_mem = (sq @ mem)/(sq.z+1e-6)  [2-term]
    hmma_gemm<5,2><<<gAM, 256, HM_SMEM2>>>(sqh, sql, mth, mtl, pamem, nullptr, nullptr, CD, CE, CD, CE, pdq, nullptr);

    // 5) causal softmax attention (QK 3-term; PV 2-term with gate-mix + split out)
    hmma_gemm<2,3><<<gQK, 256, HM_SMEM3>>>(qh, ql, kh, kl, pP, nullptr, nullptr, CD, CE, CE, CS, nullptr, nullptr);
    softmax_reg_kernel<<<dim3(CS / 8, CBH), 256>>>(pP, pph, ppl);
    tsplit_head_kernel<<<gTS, blkT>>>(pv, vth, vtl);
    hmma_gemm<3,2><<<gPV, 256, HM_SMEM2>>>(pph, ppl, vth, vtl, nullptr, mh, ml, CS, CS, CS, CE, pamem, betas);

    // 6) memory update: U = v - (sk@mem)/(sk.z+1e-6) [2-term]; mem_new [3-term]
    hmma_gemm<6,2><<<gAM, 256, HM_SMEM2>>>(skh, skl, mth, mtl, pU, nullptr, nullptr, CD, CE, CD, CE, pdk, pv);
    tsplit_head_kernel<<<gTS, blkT>>>(psk, skth, sktl);
    tsplit_head_kernel<<<gTS, blkT>>>(pU, uth, utl);
    hmma_gemm<7,3><<<gMU, 256, HM_SMEM3>>>(skth, sktl, uth, utl, outmem, nullptr, nullptr, CS, CS, CS, CD, memp, nullptr);

    // 7) output projection + bias [2-term]
    hmma_gemm<1,2><<<gProj, 256, HM_SMEM2>>>(mh, ml, woh, wol, out, nullptr, nullptr, CE, CE, CE, CE, bo, nullptr);
}